// round 1
// baseline (speedup 1.0000x reference)
#include <cuda_runtime.h>
#include <math.h>

#define B_   2
#define L_   4096
#define H_   1024
#define NH_  4
#define DK_  256
#define DV_  256
#define C_   32
#define NC_  128
#define BL_  8192
#define BH_  8
#define F1_  2048

// ------------------------- scratch (static device memory; no allocs) -------
__device__ float g_qp[BL_*H_], g_kp[BL_*H_], g_vp[BL_*H_];
__device__ float g_qs[BL_*H_], g_ks[BL_*H_], g_vs[BL_*H_];
__device__ float g_qn[BL_*H_], g_kn[BL_*H_], g_kb[BL_*H_], g_vb[BL_*H_];
__device__ float g_u [BL_*H_], g_w [BL_*H_];
__device__ float g_delta[BL_*H_], g_shrt[BL_*H_], g_long[BL_*H_], g_mix[BL_*H_];
__device__ float g_h1[BL_*F1_];
__device__ float g_att[BH_*NC_*C_*C_];
__device__ float g_beta[BL_*NH_];
__device__ float g_fw[BL_*16];

__device__ __forceinline__ float sigmoidf_(float x) { return 1.f / (1.f + expf(-x)); }
__device__ __forceinline__ float geluf_(float x) {
    return 0.5f * x * (1.f + erff(x * 0.70710678118654752440f));
}

// ------------------------- SGEMM: C[M,N] = A[M,K] @ W[K,N] ------------------
// act==0: none. act==1: gelu(x + bias[col]).
__global__ __launch_bounds__(256) void sgemm_kernel(
    const float* __restrict__ A, const float* __restrict__ W,
    const float* __restrict__ bias, float* __restrict__ C,
    int M, int N, int K, int act)
{
    __shared__ float As[8][128];
    __shared__ float Bs[8][128];
    const int tid = threadIdx.x;
    const int tx = tid & 15;          // N dir
    const int ty = tid >> 4;          // M dir
    const int row0 = blockIdx.y * 128;
    const int col0 = blockIdx.x * 128;
    const int arow = tid >> 1, acol = (tid & 1) << 2;
    const int brow = tid >> 5, bcol = (tid & 31) << 2;
    const float* Ap = A + (size_t)(row0 + arow) * K + acol;
    const float* Bp = W + (size_t)brow * N + col0 + bcol;

    float acc[8][8];
#pragma unroll
    for (int i = 0; i < 8; i++)
#pragma unroll
        for (int j = 0; j < 8; j++) acc[i][j] = 0.f;

    for (int k0 = 0; k0 < K; k0 += 8) {
        float4 av = *(const float4*)(Ap + k0);
        As[acol + 0][arow] = av.x;
        As[acol + 1][arow] = av.y;
        As[acol + 2][arow] = av.z;
        As[acol + 3][arow] = av.w;
        *(float4*)&Bs[brow][bcol] = *(const float4*)(Bp + (size_t)k0 * N);
        __syncthreads();
#pragma unroll
        for (int kk = 0; kk < 8; kk++) {
            float a[8], b[8];
            *(float4*)(a)     = *(const float4*)&As[kk][ty * 8];
            *(float4*)(a + 4) = *(const float4*)&As[kk][ty * 8 + 4];
            *(float4*)(b)     = *(const float4*)&Bs[kk][tx * 8];
            *(float4*)(b + 4) = *(const float4*)&Bs[kk][tx * 8 + 4];
#pragma unroll
            for (int i = 0; i < 8; i++)
#pragma unroll
                for (int j = 0; j < 8; j++)
                    acc[i][j] += a[i] * b[j];
        }
        __syncthreads();
    }

#pragma unroll
    for (int i = 0; i < 8; i++) {
        size_t r = (size_t)(row0 + ty * 8 + i);
#pragma unroll
        for (int j4 = 0; j4 < 8; j4 += 4) {
            int cc = col0 + tx * 8 + j4;
            float4 o;
            o.x = acc[i][j4 + 0]; o.y = acc[i][j4 + 1];
            o.z = acc[i][j4 + 2]; o.w = acc[i][j4 + 3];
            if (act == 1) {
                o.x = geluf_(o.x + bias[cc + 0]);
                o.y = geluf_(o.y + bias[cc + 1]);
                o.z = geluf_(o.z + bias[cc + 2]);
                o.w = geluf_(o.w + bias[cc + 3]);
            }
            *(float4*)&C[r * N + cc] = o;
        }
    }
}

// ------------------------- short causal depthwise conv (K=4) + silu ---------
__global__ __launch_bounds__(256) void conv4_silu_kernel(
    const float* __restrict__ x, const float* __restrict__ f, float* __restrict__ y)
{
    int idx = blockIdx.x * 256 + threadIdx.x;      // (bl, c)
    int c  = idx & (H_ - 1);
    int bl = idx >> 10;
    int l  = bl & (L_ - 1);
    float4 fv = *(const float4*)(f + c * 4);
    float acc = fv.w * x[idx];
    if (l >= 1) acc += fv.z * x[idx - H_];
    if (l >= 2) acc += fv.y * x[idx - 2 * H_];
    if (l >= 3) acc += fv.x * x[idx - 3 * H_];
    y[idx] = acc * sigmoidf_(acc);
}

// ------------------------- beta = sigmoid(hs @ Wb) --------------------------
__global__ __launch_bounds__(128) void beta_kernel(
    const float* __restrict__ hs, const float* __restrict__ Wb, float* __restrict__ beta)
{
    int bl = blockIdx.x;
    int wrp = threadIdx.x >> 5, lane = threadIdx.x & 31;
    const float* hp = hs + (size_t)bl * H_;
    float acc = 0.f;
    for (int d = lane; d < H_; d += 32) acc += hp[d] * Wb[d * NH_ + wrp];
#pragma unroll
    for (int o = 16; o; o >>= 1) acc += __shfl_xor_sync(0xffffffffu, acc, o);
    if (lane == 0) beta[bl * NH_ + wrp] = sigmoidf_(acc);
}

// ------------------------- l2norm + beta-scale + [B,H,L,D] transpose --------
__global__ __launch_bounds__(256) void normtr_kernel(
    const float* __restrict__ qs, const float* __restrict__ ks, const float* __restrict__ vs,
    const float* __restrict__ beta,
    float* __restrict__ qn, float* __restrict__ kn, float* __restrict__ kb, float* __restrict__ vb)
{
    int bl = blockIdx.x, h = blockIdx.y, d = threadIdx.x;
    int b = bl >> 12;
    int l = bl & (L_ - 1);
    size_t src = (size_t)bl * H_ + h * DK_ + d;
    float qv = qs[src], kv = ks[src], vv = vs[src];
    float s1 = qv * qv, s2 = kv * kv;
#pragma unroll
    for (int o = 16; o; o >>= 1) {
        s1 += __shfl_xor_sync(0xffffffffu, s1, o);
        s2 += __shfl_xor_sync(0xffffffffu, s2, o);
    }
    __shared__ float r1[8], r2[8];
    __shared__ float inv1, inv2;
    int lane = d & 31, wid = d >> 5;
    if (lane == 0) { r1[wid] = s1; r2[wid] = s2; }
    __syncthreads();
    if (d == 0) {
        float t1 = 0.f, t2 = 0.f;
        for (int i = 0; i < 8; i++) { t1 += r1[i]; t2 += r2[i]; }
        inv1 = rsqrtf(t1);
        inv2 = rsqrtf(t2);
    }
    __syncthreads();
    float bt = beta[bl * NH_ + h];
    size_t dst = (((size_t)b * NH_ + h) * L_ + l) * DK_ + d;
    float knv = kv * inv2;
    qn[dst] = qv * inv1;
    kn[dst] = knv;
    kb[dst] = knv * bt;
    vb[dst] = vv * bt;
}

// ------------------------- per-chunk: UT transform, u, w, attn --------------
__global__ __launch_bounds__(256) void chunk_kernel(
    const float* __restrict__ qn, const float* __restrict__ kn,
    const float* __restrict__ kb, const float* __restrict__ vb,
    float* __restrict__ U, float* __restrict__ Wm, float* __restrict__ ATT)
{
    extern __shared__ float sm[];
    float* sk  = sm;            // 32x256
    float* skb = sm + 8192;     // 32x256
    float* sx  = sm + 16384;    // 32x256 (vb then qn)
    float* T   = sm + 24576;    // 32x33
    int bh = blockIdx.x, n = blockIdx.y;
    int tid = threadIdx.x;
    size_t base = ((size_t)bh * L_ + n * C_) * DK_;

    for (int i = tid; i < 2048; i += 256) {
        ((float4*)sk)[i]  = ((const float4*)(kn + base))[i];
        ((float4*)skb)[i] = ((const float4*)(kb + base))[i];
        ((float4*)sx)[i]  = ((const float4*)(vb + base))[i];
    }
    __syncthreads();

    // A = -(kb @ kn^T) * strict_lower
    for (int e = tid; e < 1024; e += 256) {
        int i = e >> 5, j = e & 31;
        float a = 0.f;
        if (j < i) {
            const float* pi = skb + i * 256;
            const float* pj = sk + j * 256;
            for (int d = 0; d < 256; d++) a -= pi[d] * pj[d];
        }
        T[i * 33 + j] = a;
    }
    __syncthreads();

    // forward substitution (warp 0): T[i,:] += T[i,:] @ T, then diag = 1
    if (tid < 32) {
        int j = tid;
        for (int i = 1; i < 32; i++) {
            float rv = T[i * 33 + j];   // original row i, col j
            float acc = rv;
            for (int m = 1; m < i; m++)
                acc += __shfl_sync(0xffffffffu, rv, m) * T[m * 33 + j];
            __syncwarp();
            T[i * 33 + j] = acc;
            __syncwarp();
        }
        T[j * 33 + j] = 1.f;
    }
    __syncthreads();

    // u = T @ vb, w = T @ kb
    for (int idx = tid; idx < 8192; idx += 256) {
        int c = idx >> 8, d = idx & 255;
        float au = 0.f, aw = 0.f;
#pragma unroll
        for (int j = 0; j < 32; j++) {
            float t = T[c * 33 + j];
            au += t * sx[j * 256 + d];
            aw += t * skb[j * 256 + d];
        }
        U[base + idx]  = au;
        Wm[base + idx] = aw;
    }
    __syncthreads();

    // attn = (qn @ kn^T) * causal (incl diag)
    for (int i = tid; i < 2048; i += 256)
        ((float4*)sx)[i] = ((const float4*)(qn + base))[i];
    __syncthreads();
    float* att = ATT + ((size_t)bh * NC_ + n) * 1024;
    for (int e = tid; e < 1024; e += 256) {
        int c = e >> 5, j = e & 31;
        float a = 0.f;
        if (j <= c) {
            const float* pq = sx + c * 256;
            const float* pk = sk + j * 256;
            for (int d = 0; d < 256; d++) a += pq[d] * pk[d];
        }
        att[e] = a;
    }
}

// ------------------------- sequential chunk scan (dv tiled by 32) -----------
__global__ __launch_bounds__(256) void scan_kernel(
    const float* __restrict__ qn, const float* __restrict__ kn,
    const float* __restrict__ U, const float* __restrict__ Wm,
    const float* __restrict__ ATT, float* __restrict__ OUT)
{
    extern __shared__ float sm[];
    float* S   = sm;            // [256][32]
    float* sq  = sm + 8192;     // [32][256]
    float* sk  = sm + 16384;    // [32][256]
    float* sw  = sm + 24576;    // [32][256]
    float* su  = sm + 32768;    // [32][32]
    float* sut = sm + 33792;    // [32][32]
    float* sat = sm + 34816;    // [32][32]
    const int bh = blockIdx.x, tile = blockIdx.y;
    const int tid = threadIdx.x;
    const int b = bh >> 2, h = bh & 3;
    const int g = tid >> 3, eg = tid & 7;   // g: row (c) or d-group; eg: e quad

    for (int i = tid; i < 8192; i += 256) S[i] = 0.f;

    for (int n = 0; n < NC_; n++) {
        __syncthreads();
        size_t base = ((size_t)bh * L_ + n * C_) * 256;
        for (int i = tid; i < 2048; i += 256) {
            ((float4*)sq)[i] = ((const float4*)(qn + base))[i];
            ((float4*)sk)[i] = ((const float4*)(kn + base))[i];
            ((float4*)sw)[i] = ((const float4*)(Wm + base))[i];
        }
        {
            int c = tid >> 3, e4 = tid & 7;
            ((float4*)su)[tid] = *(const float4*)(U + base + c * 256 + tile * 32 + e4 * 4);
            ((float4*)sat)[tid] = ((const float4*)(ATT + ((size_t)bh * NC_ + n) * 1024))[tid];
        }
        __syncthreads();

        // wS and qS over full dk
        float4 aw = make_float4(0.f, 0.f, 0.f, 0.f);
        float4 aq = make_float4(0.f, 0.f, 0.f, 0.f);
        const float* wr = sw + g * 256;
        const float* qr = sq + g * 256;
#pragma unroll 4
        for (int d = 0; d < 256; d++) {
            float4 s4 = *(float4*)(S + d * 32 + eg * 4);
            float wv = wr[d], qv = qr[d];
            aw.x += wv * s4.x; aw.y += wv * s4.y; aw.z += wv * s4.z; aw.w += wv * s4.w;
            aq.x += qv * s4.x; aq.y += qv * s4.y; aq.z += qv * s4.z; aq.w += qv * s4.w;
        }
        float4 uv = *(float4*)(su + g * 32 + eg * 4);
        float4 ut = make_float4(uv.x - aw.x, uv.y - aw.y, uv.z - aw.z, uv.w - aw.w);
        *(float4*)(sut + g * 32 + eg * 4) = ut;
        __syncthreads();

        // o = qS + attn @ u_t
        const float* ar = sat + g * 32;
#pragma unroll
        for (int j = 0; j < 32; j++) {
            float av = ar[j];
            float4 u4 = *(float4*)(sut + j * 32 + eg * 4);
            aq.x += av * u4.x; aq.y += av * u4.y; aq.z += av * u4.z; aq.w += av * u4.w;
        }
        *(float4*)(OUT + (size_t)(b * L_ + n * C_ + g) * H_ + h * 256 + tile * 32 + eg * 4) = aq;

        // S += k^T @ u_t   (each thread owns d = g*8..g*8+7, e quad eg)
        float4 accS[8];
#pragma unroll
        for (int i = 0; i < 8; i++) accS[i] = make_float4(0.f, 0.f, 0.f, 0.f);
        for (int c = 0; c < 32; c++) {
            float4 u4 = *(float4*)(sut + c * 32 + eg * 4);
            const float* kr = sk + c * 256 + g * 8;
#pragma unroll
            for (int i = 0; i < 8; i++) {
                float kv = kr[i];
                accS[i].x += kv * u4.x; accS[i].y += kv * u4.y;
                accS[i].z += kv * u4.z; accS[i].w += kv * u4.w;
            }
        }
#pragma unroll
        for (int i = 0; i < 8; i++) {
            float4 s4 = *(float4*)(S + (g * 8 + i) * 32 + eg * 4);
            s4.x += accS[i].x; s4.y += accS[i].y; s4.z += accS[i].z; s4.w += accS[i].w;
            *(float4*)(S + (g * 8 + i) * 32 + eg * 4) = s4;
        }
    }
}

// ------------------------- FIR depthwise causal conv (generic K) ------------
__global__ __launch_bounds__(256) void fir_kernel(
    const float* __restrict__ x, const float* __restrict__ f, float* __restrict__ y, int K)
{
    int idx = blockIdx.x * 256 + threadIdx.x;
    int c  = idx & (H_ - 1);
    int bl = idx >> 10;
    int l  = bl & (L_ - 1);
    const float* fp = f + (size_t)c * K;
    float acc = 0.f;
    int t0 = K - 1 - l; if (t0 < 0) t0 = 0;
    for (int t = t0; t < K; t++)
        acc += x[idx + (t - (K - 1)) * H_] * fp[t];
    y[idx] = acc;
}

// ------------------------- fusion gate: h1 @ Wf2 + bf2 -> softmax4 ----------
__global__ __launch_bounds__(128) void gate_kernel(
    const float* __restrict__ h1, const float* __restrict__ Wf2,
    const float* __restrict__ bf2, float* __restrict__ fw)
{
    int bl = blockIdx.x, tid = threadIdx.x;
    float acc[16];
#pragma unroll
    for (int j = 0; j < 16; j++) acc[j] = 0.f;
    const float* hp = h1 + (size_t)bl * F1_;
    for (int d = tid; d < F1_; d += 128) {
        float hv = hp[d];
        const float4* w4 = (const float4*)(Wf2 + d * 16);
        float4 w0 = w4[0], w1 = w4[1], w2 = w4[2], w3 = w4[3];
        acc[0] += hv * w0.x; acc[1] += hv * w0.y; acc[2] += hv * w0.z; acc[3] += hv * w0.w;
        acc[4] += hv * w1.x; acc[5] += hv * w1.y; acc[6] += hv * w1.z; acc[7] += hv * w1.w;
        acc[8] += hv * w2.x; acc[9] += hv * w2.y; acc[10] += hv * w2.z; acc[11] += hv * w2.w;
        acc[12] += hv * w3.x; acc[13] += hv * w3.y; acc[14] += hv * w3.z; acc[15] += hv * w3.w;
    }
    __shared__ float red[16][129];
    __shared__ float logit[16];
#pragma unroll
    for (int j = 0; j < 16; j++) red[j][tid] = acc[j];
    __syncthreads();
    if (tid < 16) {
        float s = bf2[tid];
        for (int i = 0; i < 128; i++) s += red[tid][i];
        logit[tid] = s;
    }
    __syncthreads();
    if (tid < 4) {
        float l0 = logit[tid * 4], l1 = logit[tid * 4 + 1];
        float l2 = logit[tid * 4 + 2], l3 = logit[tid * 4 + 3];
        float m = fmaxf(fmaxf(l0, l1), fmaxf(l2, l3));
        float e0 = expf(l0 - m), e1 = expf(l1 - m), e2 = expf(l2 - m), e3 = expf(l3 - m);
        float inv = 1.f / (e0 + e1 + e2 + e3);
        float* o = fw + (size_t)bl * 16 + tid * 4;
        o[0] = e0 * inv; o[1] = e1 * inv; o[2] = e2 * inv; o[3] = e3 * inv;
    }
}

// ------------------------- branch mix + per-head rmsnorm --------------------
__global__ __launch_bounds__(256) void mix_rms_kernel(
    const float* __restrict__ br_s, const float* __restrict__ br_l,
    const float* __restrict__ br_d, const float* __restrict__ br_v,
    const float* __restrict__ fw, const float* __restrict__ rmsw,
    float* __restrict__ outp)
{
    int bl = blockIdx.x, h = blockIdx.y, d = threadIdx.x;
    size_t i = (size_t)bl * H_ + h * 256 + d;
    const float* f = fw + (size_t)bl * 16 + h * 4;
    float val = f[0] * br_s[i] + f[1] * br_l[i] + f[2] * br_d[i] + f[3] * br_v[i];
    float ss = val * val;
#pragma unroll
    for (int o = 16; o; o >>= 1) ss += __shfl_xor_sync(0xffffffffu, ss, o);
    __shared__ float red[8];
    __shared__ float scale;
    if ((d & 31) == 0) red[d >> 5] = ss;
    __syncthreads();
    if (d == 0) {
        float t = 0.f;
        for (int k = 0; k < 8; k++) t += red[k];
        scale = rsqrtf(t * (1.f / 256.f) + 1e-5f);
    }
    __syncthreads();
    outp[i] = val * scale * rmsw[d];
}

// ------------------------- launcher ----------------------------------------
extern "C" void kernel_launch(void* const* d_in, const int* in_sizes, int n_in,
                              void* d_out, int out_size)
{
    const float* hs   = (const float*)d_in[0];
    const float* Wq   = (const float*)d_in[1];
    const float* Wk   = (const float*)d_in[2];
    const float* Wv   = (const float*)d_in[3];
    const float* Wb   = (const float*)d_in[4];
    const float* cq   = (const float*)d_in[5];
    const float* ck   = (const float*)d_in[6];
    const float* cv   = (const float*)d_in[7];
    const float* fsw  = (const float*)d_in[8];
    const float* flw  = (const float*)d_in[9];
    const float* Wf1  = (const float*)d_in[10];
    const float* bf1  = (const float*)d_in[11];
    const float* Wf2  = (const float*)d_in[12];
    const float* bf2  = (const float*)d_in[13];
    const float* rmsw = (const float*)d_in[14];
    const float* Wo   = (const float*)d_in[15];
    float* out = (float*)d_out;

    float *qp, *kp, *vp, *qs, *ks, *vs, *qn, *kn, *kb, *vb;
    float *u, *w, *delta, *shrt, *lng, *mix, *h1, *att, *beta, *fw;
    cudaGetSymbolAddress((void**)&qp, g_qp);
    cudaGetSymbolAddress((void**)&kp, g_kp);
    cudaGetSymbolAddress((void**)&vp, g_vp);
    cudaGetSymbolAddress((void**)&qs, g_qs);
    cudaGetSymbolAddress((void**)&ks, g_ks);
    cudaGetSymbolAddress((void**)&vs, g_vs);
    cudaGetSymbolAddress((void**)&qn, g_qn);
    cudaGetSymbolAddress((void**)&kn, g_kn);
    cudaGetSymbolAddress((void**)&kb, g_kb);
    cudaGetSymbolAddress((void**)&vb, g_vb);
    cudaGetSymbolAddress((void**)&u, g_u);
    cudaGetSymbolAddress((void**)&w, g_w);
    cudaGetSymbolAddress((void**)&delta, g_delta);
    cudaGetSymbolAddress((void**)&shrt, g_shrt);
    cudaGetSymbolAddress((void**)&lng, g_long);
    cudaGetSymbolAddress((void**)&mix, g_mix);
    cudaGetSymbolAddress((void**)&h1, g_h1);
    cudaGetSymbolAddress((void**)&att, g_att);
    cudaGetSymbolAddress((void**)&beta, g_beta);
    cudaGetSymbolAddress((void**)&fw, g_fw);

    cudaFuncSetAttribute(chunk_kernel, cudaFuncAttributeMaxDynamicSharedMemorySize, 102528);
    cudaFuncSetAttribute(scan_kernel,  cudaFuncAttributeMaxDynamicSharedMemorySize, 143360);

    dim3 g1(H_ / 128, BL_ / 128);   // (8, 64)

    // projections + gate-MLP first layer
    sgemm_kernel<<<g1, 256>>>(hs, Wq, nullptr, qp, BL_, H_, H_, 0);
    sgemm_kernel<<<g1, 256>>>(hs, Wk, nullptr, kp, BL_, H_, H_, 0);
    sgemm_kernel<<<g1, 256>>>(hs, Wv, nullptr, vp, BL_, H_, H_, 0);
    sgemm_kernel<<<dim3(F1_ / 128, BL_ / 128), 256>>>(hs, Wf1, bf1, h1, BL_, F1_, H_, 1);

    // short conv + silu
    conv4_silu_kernel<<<BL_ * H_ / 256, 256>>>(qp, cq, qs);
    conv4_silu_kernel<<<BL_ * H_ / 256, 256>>>(kp, ck, ks);
    conv4_silu_kernel<<<BL_ * H_ / 256, 256>>>(vp, cv, vs);

    // beta, l2norm + transpose
    beta_kernel<<<BL_, 128>>>(hs, Wb, beta);
    normtr_kernel<<<dim3(BL_, NH_), 256>>>(qs, ks, vs, beta, qn, kn, kb, vb);

    // delta rule
    chunk_kernel<<<dim3(BH_, NC_), 256, 102528>>>(qn, kn, kb, vb, u, w, att);
    scan_kernel<<<dim3(BH_, 8), 256, 143360>>>(qn, kn, u, w, att, delta);

    // FIR branches
    fir_kernel<<<BL_ * H_ / 256, 256>>>(vs, fsw, shrt, 7);
    fir_kernel<<<BL_ * H_ / 256, 256>>>(vs, flw, lng, 64);

    // gate, mix+rmsnorm, output projection
    gate_kernel<<<BL_, 128>>>(h1, Wf2, bf2, fw);
    mix_rms_kernel<<<dim3(BL_, NH_), 256>>>(shrt, lng, delta, vs, fw, rmsw, mix);
    sgemm_kernel<<<g1, 256>>>(mix, Wo, nullptr, out, BL_, H_, H_, 0);
}

// round 4
// speedup vs baseline: 1.9056x; 1.9056x over previous
#include <cuda_runtime.h>
#include <cuda_bf16.h>
#include <math.h>
#include <stdint.h>

#define B_   2
#define L_   4096
#define H_   1024
#define NH_  4
#define DK_  256
#define DV_  256
#define C_   32
#define NC_  128
#define BL_  8192
#define BH_  8
#define F1_  2048

// ------------------------- scratch (static device memory; no allocs) -------
__device__ float g_qp[BL_*H_], g_kp[BL_*H_], g_vp[BL_*H_];
__device__ float g_qs[BL_*H_], g_ks[BL_*H_], g_vs[BL_*H_];
__device__ float g_qn[BL_*H_], g_kn[BL_*H_], g_kb[BL_*H_], g_vb[BL_*H_];
__device__ float g_u [BL_*H_], g_w [BL_*H_];
__device__ float g_delta[BL_*H_], g_shrt[BL_*H_], g_long[BL_*H_], g_mix[BL_*H_];
__device__ float g_h1[BL_*F1_];
__device__ float g_att[BH_*NC_*C_*C_];
__device__ float g_beta[BL_*NH_];
__device__ float g_fw[BL_*16];

__device__ __forceinline__ float sigmoidf_(float x) { return 1.f / (1.f + expf(-x)); }
__device__ __forceinline__ float geluf_(float x) {
    return 0.5f * x * (1.f + erff(x * 0.70710678118654752440f));
}

// ===================== warp-mma bf16 split-x3 GEMM ==========================
// C[M,N] = A[M,K] @ W[K,N], fp32 in/out. act==1: gelu(x + bias[col]).
// CTA: 128x128 tile, 256 threads (8 warps, each 32x64), BK=64.
// smem layout per operand tile: [row][32 b32], physical b32 col
//   phys = col ^ (((row&7)<<2) | ((row>>3)&3))  -> conflict-free for both
//   column-direction fills and fragment loads.

#define MMA_BF16_(c, a0, a1, a2, a3, b0, b1) \
    asm volatile("mma.sync.aligned.m16n8k16.row.col.f32.bf16.bf16.f32 " \
        "{%0,%1,%2,%3}, {%4,%5,%6,%7}, {%8,%9}, {%0,%1,%2,%3};" \
        : "+f"((c)[0]), "+f"((c)[1]), "+f"((c)[2]), "+f"((c)[3]) \
        : "r"(a0), "r"(a1), "r"(a2), "r"(a3), "r"(b0), "r"(b1))

__device__ __forceinline__ int swz_(int row, int col) {
    return col ^ (((row & 7) << 2) | ((row >> 3) & 3));
}
__device__ __forceinline__ uint32_t pack_bf16_hi_(float x, float y) {
    __nv_bfloat162 h = __halves2bfloat162(__float2bfloat16(x), __float2bfloat16(y));
    return *reinterpret_cast<uint32_t*>(&h);
}
__device__ __forceinline__ uint32_t pack_bf16_lo_(float x, float y) {
    float hx = __bfloat162float(__float2bfloat16(x));
    float hy = __bfloat162float(__float2bfloat16(y));
    __nv_bfloat162 l = __halves2bfloat162(__float2bfloat16(x - hx), __float2bfloat16(y - hy));
    return *reinterpret_cast<uint32_t*>(&l);
}

#define MG_SMEM 65536

__global__ __launch_bounds__(256) void mma_gemm_kernel(
    const float* __restrict__ A, const float* __restrict__ W,
    const float* __restrict__ bias, float* __restrict__ C,
    int N, int K, int act)
{
    extern __shared__ __align__(16) uint32_t smem_u[];
    uint32_t* Ahi = smem_u;                 // 128 rows x 32 b32
    uint32_t* Alo = smem_u + 4096;
    uint32_t* Bhi = smem_u + 8192;          // 128 n-rows x 32 b32
    uint32_t* Blo = smem_u + 12288;
    const int tid = threadIdx.x;
    const int wid = tid >> 5, lane = tid & 31;
    const int g = lane >> 2, t = lane & 3;
    const int warp_m = (wid & 3) * 32;
    const int warp_n = (wid >> 2) * 64;
    const int row0 = blockIdx.y * 128, col0 = blockIdx.x * 128;

    float acc[2][8][4];
#pragma unroll
    for (int mt = 0; mt < 2; mt++)
#pragma unroll
        for (int nt = 0; nt < 8; nt++)
#pragma unroll
            for (int e = 0; e < 4; e++) acc[mt][nt][e] = 0.f;

    for (int k0 = 0; k0 < K; k0 += 64) {
        __syncthreads();
        // ---- fill A tile [128 m][64 k]: float4 reads, 2+2 b32 stores -------
#pragma unroll
        for (int i = 0; i < 8; i++) {
            int f4 = tid + i * 256;
            int m = f4 >> 4, c4 = f4 & 15;
            float4 a = *(const float4*)(A + (size_t)(row0 + m) * K + k0 + c4 * 4);
            int j = c4 * 2;
            Ahi[m * 32 + swz_(m, j)]     = pack_bf16_hi_(a.x, a.y);
            Ahi[m * 32 + swz_(m, j + 1)] = pack_bf16_hi_(a.z, a.w);
            Alo[m * 32 + swz_(m, j)]     = pack_bf16_lo_(a.x, a.y);
            Alo[m * 32 + swz_(m, j + 1)] = pack_bf16_lo_(a.z, a.w);
        }
        // ---- fill B tile as [n][k]: k-quad per thread, coalesced over n ----
#pragma unroll
        for (int i = 0; i < 8; i++) {
            int task = tid + i * 256;          // 2048 tasks: 16 kq x 128 n
            int n  = task & 127;
            int kq = task >> 7;                // 0..15 -> k = kq*4
            const float* wp = W + (size_t)(k0 + kq * 4) * N + col0 + n;
            float w0 = wp[0];
            float w1 = wp[N];
            float w2 = wp[2 * N];
            float w3 = wp[3 * N];
            int j = kq * 2;
            Bhi[n * 32 + swz_(n, j)]     = pack_bf16_hi_(w0, w1);
            Bhi[n * 32 + swz_(n, j + 1)] = pack_bf16_hi_(w2, w3);
            Blo[n * 32 + swz_(n, j)]     = pack_bf16_lo_(w0, w1);
            Blo[n * 32 + swz_(n, j + 1)] = pack_bf16_lo_(w2, w3);
        }
        __syncthreads();

        // ---- compute: 4 k16 sub-steps --------------------------------------
#pragma unroll
        for (int ks = 0; ks < 4; ks++) {
            uint32_t ah[2][4], al[2][4];
#pragma unroll
            for (int mt = 0; mt < 2; mt++) {
                int r  = warp_m + mt * 16 + g;
                int cA = ks * 8 + t, cB = cA + 4;
                ah[mt][0] = Ahi[r * 32 + swz_(r, cA)];
                ah[mt][1] = Ahi[(r + 8) * 32 + swz_(r + 8, cA)];
                ah[mt][2] = Ahi[r * 32 + swz_(r, cB)];
                ah[mt][3] = Ahi[(r + 8) * 32 + swz_(r + 8, cB)];
                al[mt][0] = Alo[r * 32 + swz_(r, cA)];
                al[mt][1] = Alo[(r + 8) * 32 + swz_(r + 8, cA)];
                al[mt][2] = Alo[r * 32 + swz_(r, cB)];
                al[mt][3] = Alo[(r + 8) * 32 + swz_(r + 8, cB)];
            }
#pragma unroll
            for (int nt = 0; nt < 8; nt++) {
                int n  = warp_n + nt * 8 + g;
                int cA = ks * 8 + t, cB = cA + 4;
                uint32_t bh0 = Bhi[n * 32 + swz_(n, cA)];
                uint32_t bh1 = Bhi[n * 32 + swz_(n, cB)];
                uint32_t bl0 = Blo[n * 32 + swz_(n, cA)];
                uint32_t bl1 = Blo[n * 32 + swz_(n, cB)];
#pragma unroll
                for (int mt = 0; mt < 2; mt++) {
                    MMA_BF16_(acc[mt][nt], ah[mt][0], ah[mt][1], ah[mt][2], ah[mt][3], bh0, bh1);
                    MMA_BF16_(acc[mt][nt], ah[mt][0], ah[mt][1], ah[mt][2], ah[mt][3], bl0, bl1);
                    MMA_BF16_(acc[mt][nt], al[mt][0], al[mt][1], al[mt][2], al[mt][3], bh0, bh1);
                }
            }
        }
    }

    // ---- epilogue -----------------------------------------------------------
#pragma unroll
    for (int mt = 0; mt < 2; mt++) {
        int r0g = row0 + warp_m + mt * 16 + g;
#pragma unroll
        for (int nt = 0; nt < 8; nt++) {
            int c = col0 + warp_n + nt * 8 + 2 * t;
            float2 v0, v1;
            v0.x = acc[mt][nt][0]; v0.y = acc[mt][nt][1];
            v1.x = acc[mt][nt][2]; v1.y = acc[mt][nt][3];
            if (act == 1) {
                float b0 = bias[c], b1 = bias[c + 1];
                v0.x = geluf_(v0.x + b0); v0.y = geluf_(v0.y + b1);
                v1.x = geluf_(v1.x + b0); v1.y = geluf_(v1.y + b1);
            }
            *(float2*)(C + (size_t)r0g * N + c) = v0;
            *(float2*)(C + (size_t)(r0g + 8) * N + c) = v1;
        }
    }
}

// ------------------------- short causal depthwise conv (K=4) + silu ---------
__global__ __launch_bounds__(256) void conv4_silu_kernel(
    const float* __restrict__ x, const float* __restrict__ f, float* __restrict__ y)
{
    int idx = blockIdx.x * 256 + threadIdx.x;      // (bl, c)
    int c  = idx & (H_ - 1);
    int bl = idx >> 10;
    int l  = bl & (L_ - 1);
    float4 fv = *(const float4*)(f + c * 4);
    float acc = fv.w * x[idx];
    if (l >= 1) acc += fv.z * x[idx - H_];
    if (l >= 2) acc += fv.y * x[idx - 2 * H_];
    if (l >= 3) acc += fv.x * x[idx - 3 * H_];
    y[idx] = acc * sigmoidf_(acc);
}

// ------------------------- beta = sigmoid(hs @ Wb) --------------------------
__global__ __launch_bounds__(128) void beta_kernel(
    const float* __restrict__ hs, const float* __restrict__ Wb, float* __restrict__ beta)
{
    int bl = blockIdx.x;
    int wrp = threadIdx.x >> 5, lane = threadIdx.x & 31;
    const float* hp = hs + (size_t)bl * H_;
    float acc = 0.f;
    for (int d = lane; d < H_; d += 32) acc += hp[d] * Wb[d * NH_ + wrp];
#pragma unroll
    for (int o = 16; o; o >>= 1) acc += __shfl_xor_sync(0xffffffffu, acc, o);
    if (lane == 0) beta[bl * NH_ + wrp] = sigmoidf_(acc);
}

// ------------------------- l2norm + beta-scale + [B,H,L,D] transpose --------
__global__ __launch_bounds__(256) void normtr_kernel(
    const float* __restrict__ qs, const float* __restrict__ ks, const float* __restrict__ vs,
    const float* __restrict__ beta,
    float* __restrict__ qn, float* __restrict__ kn, float* __restrict__ kb, float* __restrict__ vb)
{
    int bl = blockIdx.x, h = blockIdx.y, d = threadIdx.x;
    int b = bl >> 12;
    int l = bl & (L_ - 1);
    size_t src = (size_t)bl * H_ + h * DK_ + d;
    float qv = qs[src], kv = ks[src], vv = vs[src];
    float s1 = qv * qv, s2 = kv * kv;
#pragma unroll
    for (int o = 16; o; o >>= 1) {
        s1 += __shfl_xor_sync(0xffffffffu, s1, o);
        s2 += __shfl_xor_sync(0xffffffffu, s2, o);
    }
    __shared__ float r1[8], r2[8];
    __shared__ float inv1, inv2;
    int lane = d & 31, wid = d >> 5;
    if (lane == 0) { r1[wid] = s1; r2[wid] = s2; }
    __syncthreads();
    if (d == 0) {
        float t1 = 0.f, t2 = 0.f;
        for (int i = 0; i < 8; i++) { t1 += r1[i]; t2 += r2[i]; }
        inv1 = rsqrtf(t1);
        inv2 = rsqrtf(t2);
    }
    __syncthreads();
    float bt = beta[bl * NH_ + h];
    size_t dst = (((size_t)b * NH_ + h) * L_ + l) * DK_ + d;
    float knv = kv * inv2;
    qn[dst] = qv * inv1;
    kn[dst] = knv;
    kb[dst] = knv * bt;
    vb[dst] = vv * bt;
}

// ------------------------- per-chunk: UT transform, u, w, attn --------------
__global__ __launch_bounds__(256) void chunk_kernel(
    const float* __restrict__ qn, const float* __restrict__ kn,
    const float* __restrict__ kb, const float* __restrict__ vb,
    float* __restrict__ U, float* __restrict__ Wm, float* __restrict__ ATT)
{
    extern __shared__ float sm[];
    float* sk  = sm;            // 32x256
    float* skb = sm + 8192;     // 32x256
    float* sx  = sm + 16384;    // 32x256 (vb then qn)
    float* T   = sm + 24576;    // 32x33
    int bh = blockIdx.x, n = blockIdx.y;
    int tid = threadIdx.x;
    size_t base = ((size_t)bh * L_ + n * C_) * DK_;

    for (int i = tid; i < 2048; i += 256) {
        ((float4*)sk)[i]  = ((const float4*)(kn + base))[i];
        ((float4*)skb)[i] = ((const float4*)(kb + base))[i];
        ((float4*)sx)[i]  = ((const float4*)(vb + base))[i];
    }
    __syncthreads();

    // A = -(kb @ kn^T) * strict_lower
    for (int e = tid; e < 1024; e += 256) {
        int i = e >> 5, j = e & 31;
        float a = 0.f;
        if (j < i) {
            const float* pi = skb + i * 256;
            const float* pj = sk + j * 256;
            for (int d = 0; d < 256; d++) a -= pi[d] * pj[d];
        }
        T[i * 33 + j] = a;
    }
    __syncthreads();

    // forward substitution (warp 0)
    if (tid < 32) {
        int j = tid;
        for (int i = 1; i < 32; i++) {
            float rv = T[i * 33 + j];
            float acc = rv;
            for (int m = 1; m < i; m++)
                acc += __shfl_sync(0xffffffffu, rv, m) * T[m * 33 + j];
            __syncwarp();
            T[i * 33 + j] = acc;
            __syncwarp();
        }
        T[j * 33 + j] = 1.f;
    }
    __syncthreads();

    // u = T @ vb, w = T @ kb
    for (int idx = tid; idx < 8192; idx += 256) {
        int c = idx >> 8, d = idx & 255;
        float au = 0.f, aw = 0.f;
#pragma unroll
        for (int j = 0; j < 32; j++) {
            float t = T[c * 33 + j];
            au += t * sx[j * 256 + d];
            aw += t * skb[j * 256 + d];
        }
        U[base + idx]  = au;
        Wm[base + idx] = aw;
    }
    __syncthreads();

    // attn = (qn @ kn^T) * causal
    for (int i = tid; i < 2048; i += 256)
        ((float4*)sx)[i] = ((const float4*)(qn + base))[i];
    __syncthreads();
    float* att = ATT + ((size_t)bh * NC_ + n) * 1024;
    for (int e = tid; e < 1024; e += 256) {
        int c = e >> 5, j = e & 31;
        float a = 0.f;
        if (j <= c) {
            const float* pq = sx + c * 256;
            const float* pk = sk + j * 256;
            for (int d = 0; d < 256; d++) a += pq[d] * pk[d];
        }
        att[e] = a;
    }
}

// ------------------------- sequential chunk scan (dv tiled by 32) -----------
__global__ __launch_bounds__(256) void scan_kernel(
    const float* __restrict__ qn, const float* __restrict__ kn,
    const float* __restrict__ U, const float* __restrict__ Wm,
    const float* __restrict__ ATT, float* __restrict__ OUT)
{
    extern __shared__ float sm[];
    float* S   = sm;            // [256][32]
    float* sq  = sm + 8192;     // [32][256]
    float* sk  = sm + 16384;    // [32][256]
    float* sw  = sm + 24576;    // [32][256]
    float* su  = sm + 32768;    // [32][32]
    float* sut = sm + 33792;    // [32][32]
    float* sat = sm + 34816;    // [32][32]
    const int bh = blockIdx.x, tile = blockIdx.y;
    const int tid = threadIdx.x;
    const int b = bh >> 2, h = bh & 3;
    const int g = tid >> 3, eg = tid & 7;

    for (int i = tid; i < 8192; i += 256) S[i] = 0.f;

    for (int n = 0; n < NC_; n++) {
        __syncthreads();
        size_t base = ((size_t)bh * L_ + n * C_) * 256;
        for (int i = tid; i < 2048; i += 256) {
            ((float4*)sq)[i] = ((const float4*)(qn + base))[i];
            ((float4*)sk)[i] = ((const float4*)(kn + base))[i];
            ((float4*)sw)[i] = ((const float4*)(Wm + base))[i];
        }
        {
            int c = tid >> 3, e4 = tid & 7;
            ((float4*)su)[tid] = *(const float4*)(U + base + c * 256 + tile * 32 + e4 * 4);
            ((float4*)sat)[tid] = ((const float4*)(ATT + ((size_t)bh * NC_ + n) * 1024))[tid];
        }
        __syncthreads();

        float4 aw = make_float4(0.f, 0.f, 0.f, 0.f);
        float4 aq = make_float4(0.f, 0.f, 0.f, 0.f);
        const float* wr = sw + g * 256;
        const float* qr = sq + g * 256;
#pragma unroll 4
        for (int d = 0; d < 256; d++) {
            float4 s4 = *(float4*)(S + d * 32 + eg * 4);
            float wv = wr[d], qv = qr[d];
            aw.x += wv * s4.x; aw.y += wv * s4.y; aw.z += wv * s4.z; aw.w += wv * s4.w;
            aq.x += qv * s4.x; aq.y += qv * s4.y; aq.z += qv * s4.z; aq.w += qv * s4.w;
        }
        float4 uv = *(float4*)(su + g * 32 + eg * 4);
        float4 ut = make_float4(uv.x - aw.x, uv.y - aw.y, uv.z - aw.z, uv.w - aw.w);
        *(float4*)(sut + g * 32 + eg * 4) = ut;
        __syncthreads();

        const float* ar = sat + g * 32;
#pragma unroll
        for (int j = 0; j < 32; j++) {
            float av = ar[j];
            float4 u4 = *(float4*)(sut + j * 32 + eg * 4);
            aq.x += av * u4.x; aq.y += av * u4.y; aq.z += av * u4.z; aq.w += av * u4.w;
        }
        *(float4*)(OUT + (size_t)(b * L_ + n * C_ + g) * H_ + h * 256 + tile * 32 + eg * 4) = aq;

        float4 accS[8];
#pragma unroll
        for (int i = 0; i < 8; i++) accS[i] = make_float4(0.f, 0.f, 0.f, 0.f);
        for (int c = 0; c < 32; c++) {
            float4 u4 = *(float4*)(sut + c * 32 + eg * 4);
            const float* kr = sk + c * 256 + g * 8;
#pragma unroll
            for (int i = 0; i < 8; i++) {
                float kv = kr[i];
                accS[i].x += kv * u4.x; accS[i].y += kv * u4.y;
                accS[i].z += kv * u4.z; accS[i].w += kv * u4.w;
            }
        }
#pragma unroll
        for (int i = 0; i < 8; i++) {
            float4 s4 = *(float4*)(S + (g * 8 + i) * 32 + eg * 4);
            s4.x += accS[i].x; s4.y += accS[i].y; s4.z += accS[i].z; s4.w += accS[i].w;
            *(float4*)(S + (g * 8 + i) * 32 + eg * 4) = s4;
        }
    }
}

// ------------------------- FIR depthwise causal conv (generic K) ------------
__global__ __launch_bounds__(256) void fir_kernel(
    const float* __restrict__ x, const float* __restrict__ f, float* __restrict__ y, int K)
{
    int idx = blockIdx.x * 256 + threadIdx.x;
    int c  = idx & (H_ - 1);
    int bl = idx >> 10;
    int l  = bl & (L_ - 1);
    const float* fp = f + (size_t)c * K;
    float acc = 0.f;
    int t0 = K - 1 - l; if (t0 < 0) t0 = 0;
    for (int t = t0; t < K; t++)
        acc += x[idx + (t - (K - 1)) * H_] * fp[t];
    y[idx] = acc;
}

// ------------------------- fusion gate: h1 @ Wf2 + bf2 -> softmax4 ----------
__global__ __launch_bounds__(128) void gate_kernel(
    const float* __restrict__ h1, const float* __restrict__ Wf2,
    const float* __restrict__ bf2, float* __restrict__ fw)
{
    int bl = blockIdx.x, tid = threadIdx.x;
    float acc[16];
#pragma unroll
    for (int j = 0; j < 16; j++) acc[j] = 0.f;
    const float* hp = h1 + (size_t)bl * F1_;
    for (int d = tid; d < F1_; d += 128) {
        float hv = hp[d];
        const float4* w4 = (const float4*)(Wf2 + d * 16);
        float4 w0 = w4[0], w1 = w4[1], w2 = w4[2], w3 = w4[3];
        acc[0] += hv * w0.x; acc[1] += hv * w0.y; acc[2] += hv * w0.z; acc[3] += hv * w0.w;
        acc[4] += hv * w1.x; acc[5] += hv * w1.y; acc[6] += hv * w1.z; acc[7] += hv * w1.w;
        acc[8] += hv * w2.x; acc[9] += hv * w2.y; acc[10] += hv * w2.z; acc[11] += hv * w2.w;
        acc[12] += hv * w3.x; acc[13] += hv * w3.y; acc[14] += hv * w3.z; acc[15] += hv * w3.w;
    }
    __shared__ float red[16][129];
    __shared__ float logit[16];
#pragma unroll
    for (int j = 0; j < 16; j++) red[j][tid] = acc[j];
    __syncthreads();
    if (tid < 16) {
        float s = bf2[tid];
        for (int i = 0; i < 128; i++) s += red[tid][i];
        logit[tid] = s;
    }
    __syncthreads();
    if (tid < 4) {
        float l0 = logit[tid * 4], l1 = logit[tid * 4 + 1];
        float l2 = logit[tid * 4 + 2], l3 = logit[tid * 4 + 3];
        float m = fmaxf(fmaxf(l0, l1), fmaxf(l2, l3));
        float e0 = expf(l0 - m), e1 = expf(l1 - m), e2 = expf(l2 - m), e3 = expf(l3 - m);
        float inv = 1.f / (e0 + e1 + e2 + e3);
        float* o = fw + (size_t)bl * 16 + tid * 4;
        o[0] = e0 * inv; o[1] = e1 * inv; o[2] = e2 * inv; o[3] = e3 * inv;
    }
}

// ------------------------- branch mix + per-head rmsnorm --------------------
__global__ __launch_bounds__(256) void mix_rms_kernel(
    const float* __restrict__ br_s, const float* __restrict__ br_l,
    const float* __restrict__ br_d, const float* __restrict__ br_v,
    const float* __restrict__ fw, const float* __restrict__ rmsw,
    float* __restrict__ outp)
{
    int bl = blockIdx.x, h = blockIdx.y, d = threadIdx.x;
    size_t i = (size_t)bl * H_ + h * 256 + d;
    const float* f = fw + (size_t)bl * 16 + h * 4;
    float val = f[0] * br_s[i] + f[1] * br_l[i] + f[2] * br_d[i] + f[3] * br_v[i];
    float ss = val * val;
#pragma unroll
    for (int o = 16; o; o >>= 1) ss += __shfl_xor_sync(0xffffffffu, ss, o);
    __shared__ float red[8];
    __shared__ float scale;
    if ((d & 31) == 0) red[d >> 5] = ss;
    __syncthreads();
    if (d == 0) {
        float t = 0.f;
        for (int k = 0; k < 8; k++) t += red[k];
        scale = rsqrtf(t * (1.f / 256.f) + 1e-5f);
    }
    __syncthreads();
    outp[i] = val * scale * rmsw[d];
}

// ------------------------- launcher ----------------------------------------
extern "C" void kernel_launch(void* const* d_in, const int* in_sizes, int n_in,
                              void* d_out, int out_size)
{
    const float* hs   = (const float*)d_in[0];
    const float* Wq   = (const float*)d_in[1];
    const float* Wk   = (const float*)d_in[2];
    const float* Wv   = (const float*)d_in[3];
    const float* Wb   = (const float*)d_in[4];
    const float* cq   = (const float*)d_in[5];
    const float* ck   = (const float*)d_in[6];
    const float* cv   = (const float*)d_in[7];
    const float* fsw  = (const float*)d_in[8];
    const float* flw  = (const float*)d_in[9];
    const float* Wf1  = (const float*)d_in[10];
    const float* bf1  = (const float*)d_in[11];
    const float* Wf2  = (const float*)d_in[12];
    const float* bf2  = (const float*)d_in[13];
    const float* rmsw = (const float*)d_in[14];
    const float* Wo   = (const float*)d_in[15];
    float* out = (float*)d_out;

    float *qp, *kp, *vp, *qs, *ks, *vs, *qn, *kn, *kb, *vb;
    float *u, *w, *delta, *shrt, *lng, *mix, *h1, *att, *beta, *fw;
    cudaGetSymbolAddress((void**)&qp, g_qp);
    cudaGetSymbolAddress((void**)&kp, g_kp);
    cudaGetSymbolAddress((void**)&vp, g_vp);
    cudaGetSymbolAddress((void**)&qs, g_qs);
    cudaGetSymbolAddress((void**)&ks, g_ks);
    cudaGetSymbolAddress((void**)&vs, g_vs);
    cudaGetSymbolAddress((void**)&qn, g_qn);
    cudaGetSymbolAddress((void**)&kn, g_kn);
    cudaGetSymbolAddress((void**)&kb, g_kb);
    cudaGetSymbolAddress((void**)&vb, g_vb);
    cudaGetSymbolAddress((void**)&u, g_u);
    cudaGetSymbolAddress((void**)&w, g_w);
    cudaGetSymbolAddress((void**)&delta, g_delta);
    cudaGetSymbolAddress((void**)&shrt, g_shrt);
    cudaGetSymbolAddress((void**)&lng, g_long);
    cudaGetSymbolAddress((void**)&mix, g_mix);
    cudaGetSymbolAddress((void**)&h1, g_h1);
    cudaGetSymbolAddress((void**)&att, g_att);
    cudaGetSymbolAddress((void**)&beta, g_beta);
    cudaGetSymbolAddress((void**)&fw, g_fw);

    cudaFuncSetAttribute(mma_gemm_kernel, cudaFuncAttributeMaxDynamicSharedMemorySize, MG_SMEM);
    cudaFuncSetAttribute(chunk_kernel, cudaFuncAttributeMaxDynamicSharedMemorySize, 102528);
    cudaFuncSetAttribute(scan_kernel,  cudaFuncAttributeMaxDynamicSharedMemorySize, 143360);

    // projections + gate-MLP first layer (HMMA bf16 split-x3)
    mma_gemm_kernel<<<dim3(H_ / 128, BL_ / 128), 256, MG_SMEM>>>(hs, Wq, nullptr, qp, H_, H_, 0);
    mma_gemm_kernel<<<dim3(H_ / 128, BL_ / 128), 256, MG_SMEM>>>(hs, Wk, nullptr, kp, H_, H_, 0);
    mma_gemm_kernel<<<dim3(H_ / 128, BL_ / 128), 256, MG_SMEM>>>(hs, Wv, nullptr, vp, H_, H_, 0);
    mma_gemm_kernel<<<dim3(F1_ / 128, BL_ / 128), 256, MG_SMEM>>>(hs, Wf1, bf1, h1, F1_, H_, 1);

    // short conv + silu
    conv4_silu_kernel<<<BL_ * H_ / 256, 256>>>(qp, cq, qs);
    conv4_silu_kernel<<<BL_ * H_ / 256, 256>>>(kp, ck, ks);
    conv4_silu_kernel<<<BL_ * H_ / 256, 256>>>(vp, cv, vs);

    // beta, l2norm + transpose
    beta_kernel<<<BL_, 128>>>(hs, Wb, beta);
    normtr_kernel<<<dim3(BL_, NH_), 256>>>(qs, ks, vs, beta, qn, kn, kb, vb);

    // delta rule
    chunk_kernel<<<dim3(BH_, NC_), 256, 102528>>>(qn, kn, kb, vb, u, w, att);
    scan_kernel<<<dim3(BH_, 8), 256, 143360>>>(qn, kn, u, w, att, delta);

    // FIR branches
    fir_kernel<<<BL_ * H_ / 256, 256>>>(vs, fsw, shrt, 7);
    fir_kernel<<<BL_ * H_ / 256, 256>>>(vs, flw, lng, 64);

    // gate, mix+rmsnorm, output projection
    gate_kernel<<<BL_, 128>>>(h1, Wf2, bf2, fw);
    mix_rms_kernel<<<dim3(BL_, NH_), 256>>>(shrt, lng, delta, vs, fw, rmsw, mix);
    mma_gemm_kernel<<<dim3(H_ / 128, BL_ / 128), 256, MG_SMEM>>>(mix, Wo, nullptr, out, H_, H_, 0);
}

// round 6
// speedup vs baseline: 3.4225x; 1.7960x over previous
#include <cuda_runtime.h>
#include <cuda_bf16.h>
#include <math.h>
#include <stdint.h>

#define B_   2
#define L_   4096
#define H_   1024
#define NH_  4
#define DK_  256
#define DV_  256
#define C_   32
#define NC_  128
#define BL_  8192
#define BH_  8
#define F1_  2048

// ------------------------- scratch (static device memory; no allocs) -------
__device__ float g_qp[BL_*H_], g_kp[BL_*H_], g_vp[BL_*H_];
__device__ float g_qs[BL_*H_], g_ks[BL_*H_], g_vs[BL_*H_];
__device__ float g_qn[BL_*H_], g_kn[BL_*H_], g_kb[BL_*H_], g_vb[BL_*H_];
__device__ float g_u [BL_*H_], g_w [BL_*H_];
__device__ float g_delta[BL_*H_], g_shrt[BL_*H_], g_long[BL_*H_], g_mix[BL_*H_];
__device__ float g_h1[BL_*F1_];
__device__ float g_att[BH_*NC_*C_*C_];
__device__ float g_beta[BL_*NH_];
__device__ float g_fw[BL_*16];

__device__ __forceinline__ float sigmoidf_(float x) { return 1.f / (1.f + expf(-x)); }
__device__ __forceinline__ float geluf_(float x) {
    return 0.5f * x * (1.f + erff(x * 0.70710678118654752440f));
}

// ===================== warp-mma bf16 split-x3 GEMM ==========================
// C[M,N] = A[M,K] @ W[K,N], fp32 in/out. act==1: gelu(x + bias[col]).
// CTA: 128x128 tile, 256 threads (8 warps, each 32x64), BK=64.
// __launch_bounds__(256,2): cap regs at 128 so 2 CTAs/SM co-reside; the other
// CTA's MMA phase hides this CTA's fill/sync bubble.

#define MMA_BF16_(c, a0, a1, a2, a3, b0, b1) \
    asm volatile("mma.sync.aligned.m16n8k16.row.col.f32.bf16.bf16.f32 " \
        "{%0,%1,%2,%3}, {%4,%5,%6,%7}, {%8,%9}, {%0,%1,%2,%3};" \
        : "+f"((c)[0]), "+f"((c)[1]), "+f"((c)[2]), "+f"((c)[3]) \
        : "r"(a0), "r"(a1), "r"(a2), "r"(a3), "r"(b0), "r"(b1))

__device__ __forceinline__ int swz_(int row, int col) {
    return col ^ (((row & 7) << 2) | ((row >> 3) & 3));
}
__device__ __forceinline__ uint32_t pack_bf16_hi_(float x, float y) {
    __nv_bfloat162 h = __halves2bfloat162(__float2bfloat16(x), __float2bfloat16(y));
    return *reinterpret_cast<uint32_t*>(&h);
}
__device__ __forceinline__ uint32_t pack_bf16_lo_(float x, float y) {
    float hx = __bfloat162float(__float2bfloat16(x));
    float hy = __bfloat162float(__float2bfloat16(y));
    __nv_bfloat162 l = __halves2bfloat162(__float2bfloat16(x - hx), __float2bfloat16(y - hy));
    return *reinterpret_cast<uint32_t*>(&l);
}

#define MG_SMEM 65536

__global__ __launch_bounds__(256, 2) void mma_gemm_kernel(
    const float* __restrict__ A, const float* __restrict__ W,
    const float* __restrict__ bias, float* __restrict__ C,
    int N, int K, int act)
{
    extern __shared__ __align__(16) uint32_t smem_u[];
    uint32_t* Ahi = smem_u;                 // 128 rows x 32 b32
    uint32_t* Alo = smem_u + 4096;
    uint32_t* Bhi = smem_u + 8192;          // 128 n-rows x 32 b32
    uint32_t* Blo = smem_u + 12288;
    const int tid = threadIdx.x;
    const int wid = tid >> 5, lane = tid & 31;
    const int g = lane >> 2, t = lane & 3;
    const int warp_m = (wid & 3) * 32;
    const int warp_n = (wid >> 2) * 64;
    const int row0 = blockIdx.y * 128, col0 = blockIdx.x * 128;

    float acc[2][8][4];
#pragma unroll
    for (int mt = 0; mt < 2; mt++)
#pragma unroll
        for (int nt = 0; nt < 8; nt++)
#pragma unroll
            for (int e = 0; e < 4; e++) acc[mt][nt][e] = 0.f;

    for (int k0 = 0; k0 < K; k0 += 64) {
        __syncthreads();
        // ---- fill A tile [128 m][64 k] ------------------------------------
#pragma unroll
        for (int i = 0; i < 8; i++) {
            int f4 = tid + i * 256;
            int m = f4 >> 4, c4 = f4 & 15;
            float4 a = *(const float4*)(A + (size_t)(row0 + m) * K + k0 + c4 * 4);
            int j = c4 * 2;
            Ahi[m * 32 + swz_(m, j)]     = pack_bf16_hi_(a.x, a.y);
            Ahi[m * 32 + swz_(m, j + 1)] = pack_bf16_hi_(a.z, a.w);
            Alo[m * 32 + swz_(m, j)]     = pack_bf16_lo_(a.x, a.y);
            Alo[m * 32 + swz_(m, j + 1)] = pack_bf16_lo_(a.z, a.w);
        }
        // ---- fill B tile as [n][k] ----------------------------------------
#pragma unroll
        for (int i = 0; i < 8; i++) {
            int task = tid + i * 256;          // 2048 tasks: 16 kq x 128 n
            int n  = task & 127;
            int kq = task >> 7;                // 0..15 -> k = kq*4
            const float* wp = W + (size_t)(k0 + kq * 4) * N + col0 + n;
            float w0 = wp[0];
            float w1 = wp[N];
            float w2 = wp[2 * N];
            float w3 = wp[3 * N];
            int j = kq * 2;
            Bhi[n * 32 + swz_(n, j)]     = pack_bf16_hi_(w0, w1);
            Bhi[n * 32 + swz_(n, j + 1)] = pack_bf16_hi_(w2, w3);
            Blo[n * 32 + swz_(n, j)]     = pack_bf16_lo_(w0, w1);
            Blo[n * 32 + swz_(n, j + 1)] = pack_bf16_lo_(w2, w3);
        }
        __syncthreads();

        // ---- compute: 4 k16 sub-steps -------------------------------------
#pragma unroll
        for (int ks = 0; ks < 4; ks++) {
            uint32_t ah[2][4], al[2][4];
#pragma unroll
            for (int mt = 0; mt < 2; mt++) {
                int r  = warp_m + mt * 16 + g;
                int cA = ks * 8 + t, cB = cA + 4;
                ah[mt][0] = Ahi[r * 32 + swz_(r, cA)];
                ah[mt][1] = Ahi[(r + 8) * 32 + swz_(r + 8, cA)];
                ah[mt][2] = Ahi[r * 32 + swz_(r, cB)];
                ah[mt][3] = Ahi[(r + 8) * 32 + swz_(r + 8, cB)];
                al[mt][0] = Alo[r * 32 + swz_(r, cA)];
                al[mt][1] = Alo[(r + 8) * 32 + swz_(r + 8, cA)];
                al[mt][2] = Alo[r * 32 + swz_(r, cB)];
                al[mt][3] = Alo[(r + 8) * 32 + swz_(r + 8, cB)];
            }
#pragma unroll
            for (int nt = 0; nt < 8; nt++) {
                int n  = warp_n + nt * 8 + g;
                int cA = ks * 8 + t, cB = cA + 4;
                uint32_t bh0 = Bhi[n * 32 + swz_(n, cA)];
                uint32_t bh1 = Bhi[n * 32 + swz_(n, cB)];
                uint32_t bl0 = Blo[n * 32 + swz_(n, cA)];
                uint32_t bl1 = Blo[n * 32 + swz_(n, cB)];
#pragma unroll
                for (int mt = 0; mt < 2; mt++) {
                    MMA_BF16_(acc[mt][nt], ah[mt][0], ah[mt][1], ah[mt][2], ah[mt][3], bh0, bh1);
                    MMA_BF16_(acc[mt][nt], ah[mt][0], ah[mt][1], ah[mt][2], ah[mt][3], bl0, bl1);
                    MMA_BF16_(acc[mt][nt], al[mt][0], al[mt][1], al[mt][2], al[mt][3], bh0, bh1);
                }
            }
        }
    }

    // ---- epilogue -----------------------------------------------------------
#pragma unroll
    for (int mt = 0; mt < 2; mt++) {
        int r0g = row0 + warp_m + mt * 16 + g;
#pragma unroll
        for (int nt = 0; nt < 8; nt++) {
            int c = col0 + warp_n + nt * 8 + 2 * t;
            float2 v0, v1;
            v0.x = acc[mt][nt][0]; v0.y = acc[mt][nt][1];
            v1.x = acc[mt][nt][2]; v1.y = acc[mt][nt][3];
            if (act == 1) {
                float b0 = bias[c], b1 = bias[c + 1];
                v0.x = geluf_(v0.x + b0); v0.y = geluf_(v0.y + b1);
                v1.x = geluf_(v1.x + b0); v1.y = geluf_(v1.y + b1);
            }
            *(float2*)(C + (size_t)r0g * N + c) = v0;
            *(float2*)(C + (size_t)(r0g + 8) * N + c) = v1;
        }
    }
}

// ------------------------- short causal depthwise conv (K=4) + silu ---------
__global__ __launch_bounds__(256) void conv4_silu_kernel(
    const float* __restrict__ x, const float* __restrict__ f, float* __restrict__ y)
{
    int idx = blockIdx.x * 256 + threadIdx.x;      // (bl, c)
    int c  = idx & (H_ - 1);
    int bl = idx >> 10;
    int l  = bl & (L_ - 1);
    float4 fv = *(const float4*)(f + c * 4);
    float acc = fv.w * x[idx];
    if (l >= 1) acc += fv.z * x[idx - H_];
    if (l >= 2) acc += fv.y * x[idx - 2 * H_];
    if (l >= 3) acc += fv.x * x[idx - 3 * H_];
    y[idx] = acc * sigmoidf_(acc);
}

// ------------------------- beta = sigmoid(hs @ Wb) --------------------------
__global__ __launch_bounds__(128) void beta_kernel(
    const float* __restrict__ hs, const float* __restrict__ Wb, float* __restrict__ beta)
{
    int bl = blockIdx.x;
    int wrp = threadIdx.x >> 5, lane = threadIdx.x & 31;
    const float* hp = hs + (size_t)bl * H_;
    float acc = 0.f;
    for (int d = lane; d < H_; d += 32) acc += hp[d] * Wb[d * NH_ + wrp];
#pragma unroll
    for (int o = 16; o; o >>= 1) acc += __shfl_xor_sync(0xffffffffu, acc, o);
    if (lane == 0) beta[bl * NH_ + wrp] = sigmoidf_(acc);
}

// ------------------------- l2norm + beta-scale + [B,H,L,D] transpose --------
__global__ __launch_bounds__(256) void normtr_kernel(
    const float* __restrict__ qs, const float* __restrict__ ks, const float* __restrict__ vs,
    const float* __restrict__ beta,
    float* __restrict__ qn, float* __restrict__ kn, float* __restrict__ kb, float* __restrict__ vb)
{
    int bl = blockIdx.x, h = blockIdx.y, d = threadIdx.x;
    int b = bl >> 12;
    int l = bl & (L_ - 1);
    size_t src = (size_t)bl * H_ + h * DK_ + d;
    float qv = qs[src], kv = ks[src], vv = vs[src];
    float s1 = qv * qv, s2 = kv * kv;
#pragma unroll
    for (int o = 16; o; o >>= 1) {
        s1 += __shfl_xor_sync(0xffffffffu, s1, o);
        s2 += __shfl_xor_sync(0xffffffffu, s2, o);
    }
    __shared__ float r1[8], r2[8];
    __shared__ float inv1, inv2;
    int lane = d & 31, wid = d >> 5;
    if (lane == 0) { r1[wid] = s1; r2[wid] = s2; }
    __syncthreads();
    if (d == 0) {
        float t1 = 0.f, t2 = 0.f;
        for (int i = 0; i < 8; i++) { t1 += r1[i]; t2 += r2[i]; }
        inv1 = rsqrtf(t1);
        inv2 = rsqrtf(t2);
    }
    __syncthreads();
    float bt = beta[bl * NH_ + h];
    size_t dst = (((size_t)b * NH_ + h) * L_ + l) * DK_ + d;
    float knv = kv * inv2;
    qn[dst] = qv * inv1;
    kn[dst] = knv;
    kb[dst] = knv * bt;
    vb[dst] = vv * bt;
}

// ------------------------- per-chunk: UT transform, u, w, attn --------------
__global__ __launch_bounds__(256) void chunk_kernel(
    const float* __restrict__ qn, const float* __restrict__ kn,
    const float* __restrict__ kb, const float* __restrict__ vb,
    float* __restrict__ U, float* __restrict__ Wm, float* __restrict__ ATT)
{
    extern __shared__ float sm[];
    float* sk  = sm;            // 32x256
    float* skb = sm + 8192;     // 32x256
    float* sx  = sm + 16384;    // 32x256 (vb then qn)
    float* T   = sm + 24576;    // 32x33
    int bh = blockIdx.x, n = blockIdx.y;
    int tid = threadIdx.x;
    size_t base = ((size_t)bh * L_ + n * C_) * DK_;

    for (int i = tid; i < 2048; i += 256) {
        ((float4*)sk)[i]  = ((const float4*)(kn + base))[i];
        ((float4*)skb)[i] = ((const float4*)(kb + base))[i];
        ((float4*)sx)[i]  = ((const float4*)(vb + base))[i];
    }
    __syncthreads();

    // A = -(kb @ kn^T) * strict_lower
    for (int e = tid; e < 1024; e += 256) {
        int i = e >> 5, j = e & 31;
        float a = 0.f;
        if (j < i) {
            const float* pi = skb + i * 256;
            const float* pj = sk + j * 256;
            for (int d = 0; d < 256; d++) a -= pi[d] * pj[d];
        }
        T[i * 33 + j] = a;
    }
    __syncthreads();

    // forward substitution (warp 0)
    if (tid < 32) {
        int j = tid;
        for (int i = 1; i < 32; i++) {
            float rv = T[i * 33 + j];
            float acc = rv;
            for (int m = 1; m < i; m++)
                acc += __shfl_sync(0xffffffffu, rv, m) * T[m * 33 + j];
            __syncwarp();
            T[i * 33 + j] = acc;
            __syncwarp();
        }
        T[j * 33 + j] = 1.f;
    }
    __syncthreads();

    // u = T @ vb, w = T @ kb
    for (int idx = tid; idx < 8192; idx += 256) {
        int c = idx >> 8, d = idx & 255;
        float au = 0.f, aw = 0.f;
#pragma unroll
        for (int j = 0; j < 32; j++) {
            float t = T[c * 33 + j];
            au += t * sx[j * 256 + d];
            aw += t * skb[j * 256 + d];
        }
        U[base + idx]  = au;
        Wm[base + idx] = aw;
    }
    __syncthreads();

    // attn = (qn @ kn^T) * causal
    for (int i = tid; i < 2048; i += 256)
        ((float4*)sx)[i] = ((const float4*)(qn + base))[i];
    __syncthreads();
    float* att = ATT + ((size_t)bh * NC_ + n) * 1024;
    for (int e = tid; e < 1024; e += 256) {
        int c = e >> 5, j = e & 31;
        float a = 0.f;
        if (j <= c) {
            const float* pq = sx + c * 256;
            const float* pk = sk + j * 256;
            for (int d = 0; d < 256; d++) a += pq[d] * pk[d];
        }
        att[e] = a;
    }
}

// ------------------------- sequential chunk scan (dv tiled by 16) -----------
// 128 CTAs (8 bh x 16 tiles) -> nearly whole chip busy; FFMA-issue-bound.
#define SCAN_SMEM (30720 * 4)
__global__ __launch_bounds__(256) void scan_kernel(
    const float* __restrict__ qn, const float* __restrict__ kn,
    const float* __restrict__ U, const float* __restrict__ Wm,
    const float* __restrict__ ATT, float* __restrict__ OUT)
{
    extern __shared__ float sm[];
    float* S   = sm;            // [256][16]
    float* sq  = sm + 4096;     // [32][256]
    float* sk  = sm + 12288;    // [32][256]
    float* sw  = sm + 20480;    // [32][256]
    float* su  = sm + 28672;    // [32][16]
    float* sut = sm + 29184;    // [32][16]
    float* sat = sm + 29696;    // [32][32]
    const int bh = blockIdx.x, tile = blockIdx.y;
    const int tid = threadIdx.x;
    const int b = bh >> 2, h = bh & 3;
    const int g = tid >> 3, eg = tid & 7;   // g: row c / d-octet; eg: e pair

    for (int i = tid; i < 4096; i += 256) S[i] = 0.f;

    for (int n = 0; n < NC_; n++) {
        __syncthreads();
        size_t base = ((size_t)bh * L_ + n * C_) * 256;
        for (int i = tid; i < 2048; i += 256) {
            ((float4*)sq)[i] = ((const float4*)(qn + base))[i];
            ((float4*)sk)[i] = ((const float4*)(kn + base))[i];
            ((float4*)sw)[i] = ((const float4*)(Wm + base))[i];
        }
        if (tid < 128) {
            int c = tid >> 2, e4 = tid & 3;
            ((float4*)su)[tid] = *(const float4*)(U + base + c * 256 + tile * 16 + e4 * 4);
        }
        ((float4*)sat)[tid] = ((const float4*)(ATT + ((size_t)bh * NC_ + n) * 1024))[tid];
        __syncthreads();

        // u_t = u - w@S ; o_partial = q@S   (full dk = 256)
        float2 aw = make_float2(0.f, 0.f);
        float2 aq = make_float2(0.f, 0.f);
        const float* wr = sw + g * 256;
        const float* qr = sq + g * 256;
#pragma unroll 8
        for (int d = 0; d < 256; d++) {
            float2 s2 = *(float2*)(S + d * 16 + eg * 2);
            float wv = wr[d], qv = qr[d];
            aw.x += wv * s2.x; aw.y += wv * s2.y;
            aq.x += qv * s2.x; aq.y += qv * s2.y;
        }
        float2 uv = *(float2*)(su + g * 16 + eg * 2);
        float2 ut = make_float2(uv.x - aw.x, uv.y - aw.y);
        *(float2*)(sut + g * 16 + eg * 2) = ut;
        __syncthreads();

        // o = q@S + attn @ u_t
        const float* ar = sat + g * 32;
#pragma unroll
        for (int j = 0; j < 32; j++) {
            float av = ar[j];
            float2 u2 = *(float2*)(sut + j * 16 + eg * 2);
            aq.x += av * u2.x; aq.y += av * u2.y;
        }
        *(float2*)(OUT + (size_t)(b * L_ + n * C_ + g) * H_ + h * 256 + tile * 16 + eg * 2) = aq;

        // S += k^T @ u_t : thread owns d octet g*8.., e pair eg
        float2 accS[8];
#pragma unroll
        for (int i = 0; i < 8; i++) accS[i] = make_float2(0.f, 0.f);
        for (int c2 = 0; c2 < 32; c2++) {
            float2 u2 = *(float2*)(sut + c2 * 16 + eg * 2);
            const float* kr = sk + c2 * 256 + g * 8;
            float4 k0 = *(const float4*)(kr);
            float4 k1 = *(const float4*)(kr + 4);
            accS[0].x += k0.x * u2.x; accS[0].y += k0.x * u2.y;
            accS[1].x += k0.y * u2.x; accS[1].y += k0.y * u2.y;
            accS[2].x += k0.z * u2.x; accS[2].y += k0.z * u2.y;
            accS[3].x += k0.w * u2.x; accS[3].y += k0.w * u2.y;
            accS[4].x += k1.x * u2.x; accS[4].y += k1.x * u2.y;
            accS[5].x += k1.y * u2.x; accS[5].y += k1.y * u2.y;
            accS[6].x += k1.z * u2.x; accS[6].y += k1.z * u2.y;
            accS[7].x += k1.w * u2.x; accS[7].y += k1.w * u2.y;
        }
#pragma unroll
        for (int i = 0; i < 8; i++) {
            float2 s2 = *(float2*)(S + (g * 8 + i) * 16 + eg * 2);
            s2.x += accS[i].x; s2.y += accS[i].y;
            *(float2*)(S + (g * 8 + i) * 16 + eg * 2) = s2;
        }
    }
}

// ------------------------- FIR depthwise causal conv (generic K, for K=7) ---
__global__ __launch_bounds__(256) void fir_kernel(
    const float* __restrict__ x, const float* __restrict__ f, float* __restrict__ y, int K)
{
    int idx = blockIdx.x * 256 + threadIdx.x;
    int c  = idx & (H_ - 1);
    int bl = idx >> 10;
    int l  = bl & (L_ - 1);
    const float* fp = f + (size_t)c * K;
    float acc = 0.f;
    int t0 = K - 1 - l; if (t0 < 0) t0 = 0;
    for (int t = t0; t < K; t++)
        acc += x[idx + (t - (K - 1)) * H_] * fp[t];
    y[idx] = acc;
}

// ------------------------- FIR K=64: smem tile + register sliding window ----
// Tile: 64 l x 128 c, halo 63 rows. sx[127][128], sf[64][129] (transposed,
// pad 129 -> conflict-free). Each thread: fixed c, 32 l-outputs in regs.
#define FIR64_SMEM ((127 * 128 + 64 * 129) * 4)
__global__ __launch_bounds__(256) void fir64_smem_kernel(
    const float* __restrict__ x, const float* __restrict__ f, float* __restrict__ y)
{
    extern __shared__ float fsm[];
    float* sx = fsm;                 // 127 x 128
    float* sf = fsm + 127 * 128;     // 64 x 129
    const int ctile = blockIdx.x & 7;
    const int ltile = blockIdx.x >> 3;
    const int l0 = ltile * 64;           // global bl start
    const int lb = l0 & (L_ - 1);        // position within batch
    const int c0 = ctile * 128;
    const int tid = threadIdx.x;

    // filters transposed: sf[t*129 + c]
    for (int i = tid; i < 64 * 128; i += 256) {
        int c = i >> 6, t = i & 63;
        sf[t * 129 + c] = f[(size_t)(c0 + c) * 64 + t];
    }
    // x rows j=0..126 -> bl = l0 + j - 63 (zeros before batch start)
    for (int i = tid; i < 127 * 128; i += 256) {
        int j = i >> 7, c = i & 127;
        int lrel = lb + j - 63;
        float v = 0.f;
        if (lrel >= 0)
            v = x[(size_t)(l0 + j - 63) * H_ + c0 + c];
        sx[j * 128 + c] = v;
    }
    __syncthreads();

    const int c = tid & 127;
    const int lg = (tid >> 7) * 32;      // 0 or 32
    float acc[32], win[32];
#pragma unroll
    for (int i = 0; i < 32; i++) acc[i] = 0.f;
#pragma unroll
    for (int i = 0; i < 32; i++) win[i] = sx[(lg + i) * 128 + c];
#pragma unroll
    for (int t = 0; t < 64; t++) {
        float ft = sf[t * 129 + c];
#pragma unroll
        for (int i = 0; i < 32; i++) acc[i] += ft * win[i];
        if (t < 63) {
#pragma unroll
            for (int i = 0; i < 31; i++) win[i] = win[i + 1];
            win[31] = sx[(lg + t + 32) * 128 + c];
        }
    }
#pragma unroll
    for (int i = 0; i < 32; i++)
        y[(size_t)(l0 + lg + i) * H_ + c0 + c] = acc[i];
}

// ------------------------- fusion gate: h1 @ Wf2 + bf2 -> softmax4 ----------
__global__ __launch_bounds__(128) void gate_kernel(
    const float* __restrict__ h1, const float* __restrict__ Wf2,
    const float* __restrict__ bf2, float* __restrict__ fw)
{
    int bl = blockIdx.x, tid = threadIdx.x;
    float acc[16];
#pragma unroll
    for (int j = 0; j < 16; j++) acc[j] = 0.f;
    const float* hp = h1 + (size_t)bl * F1_;
    for (int d = tid; d < F1_; d += 128) {
        float hv = hp[d];
        const float4* w4 = (const float4*)(Wf2 + d * 16);
        float4 w0 = w4[0], w1 = w4[1], w2 = w4[2], w3 = w4[3];
        acc[0] += hv * w0.x; acc[1] += hv * w0.y; acc[2] += hv * w0.z; acc[3] += hv * w0.w;
        acc[4] += hv * w1.x; acc[5] += hv * w1.y; acc[6] += hv * w1.z; acc[7] += hv * w1.w;
        acc[8] += hv * w2.x; acc[9] += hv * w2.y; acc[10] += hv * w2.z; acc[11] += hv * w2.w;
        acc[12] += hv * w3.x; acc[13] += hv * w3.y; acc[14] += hv * w3.z; acc[15] += hv * w3.w;
    }
    __shared__ float red[16][129];
    __shared__ float logit[16];
#pragma unroll
    for (int j = 0; j < 16; j++) red[j][tid] = acc[j];
    __syncthreads();
    if (tid < 16) {
        float s = bf2[tid];
        for (int i = 0; i < 128; i++) s += red[tid][i];
        logit[tid] = s;
    }
    __syncthreads();
    if (tid < 4) {
        float l0 = logit[tid * 4], l1 = logit[tid * 4 + 1];
        float l2 = logit[tid * 4 + 2], l3 = logit[tid * 4 + 3];
        float m = fmaxf(fmaxf(l0, l1), fmaxf(l2, l3));
        float e0 = expf(l0 - m), e1 = expf(l1 - m), e2 = expf(l2 - m), e3 = expf(l3 - m);
        float inv = 1.f / (e0 + e1 + e2 + e3);
        float* o = fw + (size_t)bl * 16 + tid * 4;
        o[0] = e0 * inv; o[1] = e1 * inv; o[2] = e2 * inv; o[3] = e3 * inv;
    }
}

// ------------------------- branch mix + per-head rmsnorm --------------------
__global__ __launch_bounds__(256) void mix_rms_kernel(
    const float* __restrict__ br_s, const float* __restrict__ br_l,
    const float* __restrict__ br_d, const float* __restrict__ br_v,
    const float* __restrict__ fw, const float* __restrict__ rmsw,
    float* __restrict__ outp)
{
    int bl = blockIdx.x, h = blockIdx.y, d = threadIdx.x;
    size_t i = (size_t)bl * H_ + h * 256 + d;
    const float* f = fw + (size_t)bl * 16 + h * 4;
    float val = f[0] * br_s[i] + f[1] * br_l[i] + f[2] * br_d[i] + f[3] * br_v[i];
    float ss = val * val;
#pragma unroll
    for (int o = 16; o; o >>= 1) ss += __shfl_xor_sync(0xffffffffu, ss, o);
    __shared__ float red[8];
    __shared__ float scale;
    if ((d & 31) == 0) red[d >> 5] = ss;
    __syncthreads();
    if (d == 0) {
        float t = 0.f;
        for (int k = 0; k < 8; k++) t += red[k];
        scale = rsqrtf(t * (1.f / 256.f) + 1e-5f);
    }
    __syncthreads();
    outp[i] = val * scale * rmsw[d];
}

// ------------------------- launcher ----------------------------------------
extern "C" void kernel_launch(void* const* d_in, const int* in_sizes, int n_in,
                              void* d_out, int out_size)
{
    const float* hs   = (const float*)d_in[0];
    const float* Wq   = (const float*)d_in[1];
    const float* Wk   = (const float*)d_in[2];
    const float* Wv   = (const float*)d_in[3];
    const float* Wb   = (const float*)d_in[4];
    const float* cq   = (const float*)d_in[5];
    const float* ck   = (const float*)d_in[6];
    const float* cv   = (const float*)d_in[7];
    const float* fsw  = (const float*)d_in[8];
    const float* flw  = (const float*)d_in[9];
    const float* Wf1  = (const float*)d_in[10];
    const float* bf1  = (const float*)d_in[11];
    const float* Wf2  = (const float*)d_in[12];
    const float* bf2  = (const float*)d_in[13];
    const float* rmsw = (const float*)d_in[14];
    const float* Wo   = (const float*)d_in[15];
    float* out = (float*)d_out;

    float *qp, *kp, *vp, *qs, *ks, *vs, *qn, *kn, *kb, *vb;
    float *u, *w, *delta, *shrt, *lng, *mix, *h1, *att, *beta, *fw;
    cudaGetSymbolAddress((void**)&qp, g_qp);
    cudaGetSymbolAddress((void**)&kp, g_kp);
    cudaGetSymbolAddress((void**)&vp, g_vp);
    cudaGetSymbolAddress((void**)&qs, g_qs);
    cudaGetSymbolAddress((void**)&ks, g_ks);
    cudaGetSymbolAddress((void**)&vs, g_vs);
    cudaGetSymbolAddress((void**)&qn, g_qn);
    cudaGetSymbolAddress((void**)&kn, g_kn);
    cudaGetSymbolAddress((void**)&kb, g_kb);
    cudaGetSymbolAddress((void**)&vb, g_vb);
    cudaGetSymbolAddress((void**)&u, g_u);
    cudaGetSymbolAddress((void**)&w, g_w);
    cudaGetSymbolAddress((void**)&delta, g_delta);
    cudaGetSymbolAddress((void**)&shrt, g_shrt);
    cudaGetSymbolAddress((void**)&lng, g_long);
    cudaGetSymbolAddress((void**)&mix, g_mix);
    cudaGetSymbolAddress((void**)&h1, g_h1);
    cudaGetSymbolAddress((void**)&att, g_att);
    cudaGetSymbolAddress((void**)&beta, g_beta);
    cudaGetSymbolAddress((void**)&fw, g_fw);

    cudaFuncSetAttribute(mma_gemm_kernel, cudaFuncAttributeMaxDynamicSharedMemorySize, MG_SMEM);
    cudaFuncSetAttribute(chunk_kernel, cudaFuncAttributeMaxDynamicSharedMemorySize, 102528);
    cudaFuncSetAttribute(scan_kernel,  cudaFuncAttributeMaxDynamicSharedMemorySize, SCAN_SMEM);
    cudaFuncSetAttribute(fir64_smem_kernel, cudaFuncAttributeMaxDynamicSharedMemorySize, FIR64_SMEM);

    // projections + gate-MLP first layer (HMMA bf16 split-x3)
    mma_gemm_kernel<<<dim3(H_ / 128, BL_ / 128), 256, MG_SMEM>>>(hs, Wq, nullptr, qp, H_, H_, 0);
    mma_gemm_kernel<<<dim3(H_ / 128, BL_ / 128), 256, MG_SMEM>>>(hs, Wk, nullptr, kp, H_, H_, 0);
    mma_gemm_kernel<<<dim3(H_ / 128, BL_ / 128), 256, MG_SMEM>>>(hs, Wv, nullptr, vp, H_, H_, 0);
    mma_gemm_kernel<<<dim3(F1_ / 128, BL_ / 128), 256, MG_SMEM>>>(hs, Wf1, bf1, h1, F1_, H_, 1);

    // short conv + silu
    conv4_silu_kernel<<<BL_ * H_ / 256, 256>>>(qp, cq, qs);
    conv4_silu_kernel<<<BL_ * H_ / 256, 256>>>(kp, ck, ks);
    conv4_silu_kernel<<<BL_ * H_ / 256, 256>>>(vp, cv, vs);

    // beta, l2norm + transpose
    beta_kernel<<<BL_, 128>>>(hs, Wb, beta);
    normtr_kernel<<<dim3(BL_, NH_), 256>>>(qs, ks, vs, beta, qn, kn, kb, vb);

    // delta rule
    chunk_kernel<<<dim3(BH_, NC_), 256, 102528>>>(qn, kn, kb, vb, u, w, att);
    scan_kernel<<<dim3(BH_, 16), 256, SCAN_SMEM>>>(qn, kn, u, w, att, delta);

    // FIR branches
    fir_kernel<<<BL_ * H_ / 256, 256>>>(vs, fsw, shrt, 7);
    fir64_smem_kernel<<<1024, 256, FIR64_SMEM>>>(vs, flw, lng);

    // gate, mix+rmsnorm, output projection
    gate_kernel<<<BL_, 128>>>(h1, Wf2, bf2, fw);
    mix_rms_kernel<<<dim3(BL_, NH_), 256>>>(shrt, lng, delta, vs, fw, rmsw, mix);
    mma_gemm_kernel<<<dim3(H_ / 128, BL_ / 128), 256, MG_SMEM>>>(mix, Wo, nullptr, out, H_, H_, 0);
}

// round 7
// speedup vs baseline: 3.8266x; 1.1181x over previous
#include <cuda_runtime.h>
#include <cuda_bf16.h>
#include <math.h>
#include <stdint.h>

#define B_   2
#define L_   4096
#define H_   1024
#define NH_  4
#define DK_  256
#define DV_  256
#define C_   32
#define NC_  128
#define BL_  8192
#define BH_  8
#define F1_  2048
#define NQKV 3072

// ------------------------- scratch (static device memory; no allocs) -------
__device__ float g_qkvp[BL_*NQKV];
__device__ float g_qs[BL_*H_], g_ks[BL_*H_], g_vs[BL_*H_];
__device__ float g_qn[BL_*H_], g_kn[BL_*H_], g_kb[BL_*H_], g_vb[BL_*H_];
__device__ float g_u [BL_*H_], g_w [BL_*H_];
__device__ float g_delta[BL_*H_], g_shrt[BL_*H_], g_long[BL_*H_];
__device__ float g_h1[BL_*F1_];
__device__ float g_att[BH_*NC_*C_*C_];
__device__ float g_beta[BL_*NH_];
__device__ float g_fw[BL_*16];
// bf16 hi/lo staging
__device__ __nv_bfloat16 g_ahi[BL_*H_],  g_alo[BL_*H_];
__device__ __nv_bfloat16 g_mhi[BL_*H_],  g_mlo[BL_*H_];
__device__ __nv_bfloat16 g_wqkv_hi[NQKV*H_], g_wqkv_lo[NQKV*H_];
__device__ __nv_bfloat16 g_wf1_hi[F1_*H_],   g_wf1_lo[F1_*H_];
__device__ __nv_bfloat16 g_wo_hi[H_*H_],     g_wo_lo[H_*H_];

__device__ __forceinline__ float sigmoidf_(float x) { return 1.f / (1.f + expf(-x)); }
__device__ __forceinline__ float geluf_(float x) {
    return 0.5f * x * (1.f + erff(x * 0.70710678118654752440f));
}
__device__ __forceinline__ uint32_t smem_u32_(const void* p) {
    uint32_t a;
    asm("{ .reg .u64 t; cvta.to.shared.u64 t, %1; cvt.u32.u64 %0, t; }" : "=r"(a) : "l"(p));
    return a;
}
__device__ __forceinline__ uint32_t pack_bf16_hi_(float x, float y) {
    __nv_bfloat162 h = __halves2bfloat162(__float2bfloat16(x), __float2bfloat16(y));
    return *reinterpret_cast<uint32_t*>(&h);
}
__device__ __forceinline__ uint32_t pack_bf16_lo_(float x, float y) {
    float hx = __bfloat162float(__float2bfloat16(x));
    float hy = __bfloat162float(__float2bfloat16(y));
    __nv_bfloat162 l = __halves2bfloat162(__float2bfloat16(x - hx), __float2bfloat16(y - hy));
    return *reinterpret_cast<uint32_t*>(&l);
}
__device__ __forceinline__ void cp16_(uint32_t dst, const void* src) {
    asm volatile("cp.async.ca.shared.global [%0], [%1], 16;" :: "r"(dst), "l"(src));
}

// ------------------------- prep: fp32 -> bf16 hi/lo ------------------------
__global__ __launch_bounds__(256) void cvt_a_kernel(
    const float* __restrict__ x, __nv_bfloat16* __restrict__ hi, __nv_bfloat16* __restrict__ lo)
{
    int i = (blockIdx.x * 256 + threadIdx.x) * 4;
    float4 v = *(const float4*)(x + i);
    uint2 oh, ol;
    oh.x = pack_bf16_hi_(v.x, v.y); oh.y = pack_bf16_hi_(v.z, v.w);
    ol.x = pack_bf16_lo_(v.x, v.y); ol.y = pack_bf16_lo_(v.z, v.w);
    *(uint2*)(hi + i) = oh;
    *(uint2*)(lo + i) = ol;
}

// W [K][N] -> Wt hi/lo [N][K]  (32x32 smem transpose)
__global__ __launch_bounds__(256) void cvt_wt_kernel(
    const float* __restrict__ W, __nv_bfloat16* __restrict__ hi, __nv_bfloat16* __restrict__ lo,
    int K, int N)
{
    __shared__ float tile[32][33];
    int n0 = blockIdx.x * 32, k0 = blockIdx.y * 32;
    int tx = threadIdx.x & 31, ty = threadIdx.x >> 5;   // 32 x 8
#pragma unroll
    for (int i = 0; i < 4; i++)
        tile[ty + 8 * i][tx] = W[(size_t)(k0 + ty + 8 * i) * N + n0 + tx];
    __syncthreads();
#pragma unroll
    for (int i = 0; i < 4; i++) {
        float v = tile[tx][ty + 8 * i];
        __nv_bfloat16 h = __float2bfloat16(v);
        size_t o = (size_t)(n0 + ty + 8 * i) * K + k0 + tx;
        hi[o] = h;
        lo[o] = __float2bfloat16(v - __bfloat162float(h));
    }
}

// ===================== warp-mma bf16 split-x3 GEMM (pre-converted) ==========
// C[M,N] = A[M,K] @ B^T[N,K], A/B given as bf16 hi/lo. act==1: gelu(+bias).
// CTA 128x128, 8 warps (32x64), BK=64; fills via cp.async 16B.
#define MMA_BF16_(c, a0, a1, a2, a3, b0, b1) \
    asm volatile("mma.sync.aligned.m16n8k16.row.col.f32.bf16.bf16.f32 " \
        "{%0,%1,%2,%3}, {%4,%5,%6,%7}, {%8,%9}, {%0,%1,%2,%3};" \
        : "+f"((c)[0]), "+f"((c)[1]), "+f"((c)[2]), "+f"((c)[3]) \
        : "r"(a0), "r"(a1), "r"(a2), "r"(a3), "r"(b0), "r"(b1))

#define MG_SMEM 65536

__device__ __forceinline__ uint32_t frag_(const uint32_t* sm, int base, int row, int j) {
    return sm[base + row * 32 + ((((j >> 2) ^ (row & 7)) << 2) | (j & 3))];
}

__global__ __launch_bounds__(256, 2) void mma_gemm2_kernel(
    const __nv_bfloat16* __restrict__ Ahi_g, const __nv_bfloat16* __restrict__ Alo_g,
    const __nv_bfloat16* __restrict__ Bhi_g, const __nv_bfloat16* __restrict__ Blo_g,
    const float* __restrict__ bias, float* __restrict__ C,
    int N, int K, int act)
{
    extern __shared__ __align__(16) uint32_t smem_u[];
    const uint32_t smem_b = smem_u32_(smem_u);
    const int tid = threadIdx.x;
    const int wid = tid >> 5, lane = tid & 31;
    const int g = lane >> 2, t = lane & 3;
    const int warp_m = (wid & 3) * 32;
    const int warp_n = (wid >> 2) * 64;
    const int row0 = blockIdx.y * 128, col0 = blockIdx.x * 128;

    float acc[2][8][4];
#pragma unroll
    for (int mt = 0; mt < 2; mt++)
#pragma unroll
        for (int nt = 0; nt < 8; nt++)
#pragma unroll
            for (int e = 0; e < 4; e++) acc[mt][nt][e] = 0.f;

    for (int k0 = 0; k0 < K; k0 += 64) {
        __syncthreads();
        // ---- fill 4 tiles via cp.async: op 0=Ahi 1=Alo 2=Bhi 3=Blo ---------
#pragma unroll
        for (int i = 0; i < 16; i++) {
            const int op = i >> 2;
            int rem = (i & 3) * 256 + tid;     // 0..1023
            int row = rem >> 3, c = rem & 7;
            const __nv_bfloat16* gsrc =
                (op == 0) ? Ahi_g + (size_t)(row0 + row) * K + k0 + c * 8 :
                (op == 1) ? Alo_g + (size_t)(row0 + row) * K + k0 + c * 8 :
                (op == 2) ? Bhi_g + (size_t)(col0 + row) * K + k0 + c * 8 :
                            Blo_g + (size_t)(col0 + row) * K + k0 + c * 8;
            uint32_t dst = smem_b + (uint32_t)(((op << 12) + row * 32 + ((c ^ (row & 7)) << 2)) << 2);
            cp16_(dst, gsrc);
        }
        asm volatile("cp.async.commit_group;");
        asm volatile("cp.async.wait_group 0;");
        __syncthreads();

        // ---- compute: 4 k16 sub-steps -------------------------------------
#pragma unroll
        for (int ks = 0; ks < 4; ks++) {
            uint32_t ah[2][4], al[2][4];
#pragma unroll
            for (int mt = 0; mt < 2; mt++) {
                int r  = warp_m + mt * 16 + g;
                int cA = ks * 8 + t, cB = cA + 4;
                ah[mt][0] = frag_(smem_u, 0, r, cA);
                ah[mt][1] = frag_(smem_u, 0, r + 8, cA);
                ah[mt][2] = frag_(smem_u, 0, r, cB);
                ah[mt][3] = frag_(smem_u, 0, r + 8, cB);
                al[mt][0] = frag_(smem_u, 4096, r, cA);
                al[mt][1] = frag_(smem_u, 4096, r + 8, cA);
                al[mt][2] = frag_(smem_u, 4096, r, cB);
                al[mt][3] = frag_(smem_u, 4096, r + 8, cB);
            }
#pragma unroll
            for (int nt = 0; nt < 8; nt++) {
                int n  = warp_n + nt * 8 + g;
                int cA = ks * 8 + t, cB = cA + 4;
                uint32_t bh0 = frag_(smem_u, 8192, n, cA);
                uint32_t bh1 = frag_(smem_u, 8192, n, cB);
                uint32_t bl0 = frag_(smem_u, 12288, n, cA);
                uint32_t bl1 = frag_(smem_u, 12288, n, cB);
#pragma unroll
                for (int mt = 0; mt < 2; mt++) {
                    MMA_BF16_(acc[mt][nt], ah[mt][0], ah[mt][1], ah[mt][2], ah[mt][3], bh0, bh1);
                    MMA_BF16_(acc[mt][nt], ah[mt][0], ah[mt][1], ah[mt][2], ah[mt][3], bl0, bl1);
                    MMA_BF16_(acc[mt][nt], al[mt][0], al[mt][1], al[mt][2], al[mt][3], bh0, bh1);
                }
            }
        }
    }

    // ---- epilogue -----------------------------------------------------------
#pragma unroll
    for (int mt = 0; mt < 2; mt++) {
        int r0g = row0 + warp_m + mt * 16 + g;
#pragma unroll
        for (int nt = 0; nt < 8; nt++) {
            int c = col0 + warp_n + nt * 8 + 2 * t;
            float2 v0, v1;
            v0.x = acc[mt][nt][0]; v0.y = acc[mt][nt][1];
            v1.x = acc[mt][nt][2]; v1.y = acc[mt][nt][3];
            if (act == 1) {
                float b0 = bias[c], b1 = bias[c + 1];
                v0.x = geluf_(v0.x + b0); v0.y = geluf_(v0.y + b1);
                v1.x = geluf_(v1.x + b0); v1.y = geluf_(v1.y + b1);
            }
            *(float2*)(C + (size_t)r0g * N + c) = v0;
            *(float2*)(C + (size_t)(r0g + 8) * N + c) = v1;
        }
    }
}

// ------------------------- short causal depthwise conv (K=4) + silu ---------
__global__ __launch_bounds__(256) void conv4_silu_kernel(
    const float* __restrict__ x, const float* __restrict__ f, float* __restrict__ y,
    int xstride, int xoff)
{
    int idx = blockIdx.x * 256 + threadIdx.x;      // (bl, c)
    int c  = idx & (H_ - 1);
    int bl = idx >> 10;
    int l  = bl & (L_ - 1);
    const float* xp = x + (size_t)bl * xstride + xoff + c;
    float4 fv = *(const float4*)(f + c * 4);
    float acc = fv.w * xp[0];
    if (l >= 1) acc += fv.z * xp[-xstride];
    if (l >= 2) acc += fv.y * xp[-2 * xstride];
    if (l >= 3) acc += fv.x * xp[-3 * xstride];
    y[idx] = acc * sigmoidf_(acc);
}

// ------------------------- beta = sigmoid(hs @ Wb) --------------------------
__global__ __launch_bounds__(128) void beta_kernel(
    const float* __restrict__ hs, const float* __restrict__ Wb, float* __restrict__ beta)
{
    int bl = blockIdx.x;
    int wrp = threadIdx.x >> 5, lane = threadIdx.x & 31;
    const float* hp = hs + (size_t)bl * H_;
    float acc = 0.f;
    for (int d = lane; d < H_; d += 32) acc += hp[d] * Wb[d * NH_ + wrp];
#pragma unroll
    for (int o = 16; o; o >>= 1) acc += __shfl_xor_sync(0xffffffffu, acc, o);
    if (lane == 0) beta[bl * NH_ + wrp] = sigmoidf_(acc);
}

// ------------------------- l2norm + beta-scale + [B,H,L,D] transpose --------
__global__ __launch_bounds__(256) void normtr_kernel(
    const float* __restrict__ qs, const float* __restrict__ ks, const float* __restrict__ vs,
    const float* __restrict__ beta,
    float* __restrict__ qn, float* __restrict__ kn, float* __restrict__ kb, float* __restrict__ vb)
{
    int bl = blockIdx.x, h = blockIdx.y, d = threadIdx.x;
    int b = bl >> 12;
    int l = bl & (L_ - 1);
    size_t src = (size_t)bl * H_ + h * DK_ + d;
    float qv = qs[src], kv = ks[src], vv = vs[src];
    float s1 = qv * qv, s2 = kv * kv;
#pragma unroll
    for (int o = 16; o; o >>= 1) {
        s1 += __shfl_xor_sync(0xffffffffu, s1, o);
        s2 += __shfl_xor_sync(0xffffffffu, s2, o);
    }
    __shared__ float r1[8], r2[8];
    __shared__ float inv1, inv2;
    int lane = d & 31, wid = d >> 5;
    if (lane == 0) { r1[wid] = s1; r2[wid] = s2; }
    __syncthreads();
    if (d == 0) {
        float t1 = 0.f, t2 = 0.f;
        for (int i = 0; i < 8; i++) { t1 += r1[i]; t2 += r2[i]; }
        inv1 = rsqrtf(t1);
        inv2 = rsqrtf(t2);
    }
    __syncthreads();
    float bt = beta[bl * NH_ + h];
    size_t dst = (((size_t)b * NH_ + h) * L_ + l) * DK_ + d;
    float knv = kv * inv2;
    qn[dst] = qv * inv1;
    kn[dst] = knv;
    kb[dst] = knv * bt;
    vb[dst] = vv * bt;
}

// ------------------------- per-chunk: UT transform, u, w, attn --------------
__global__ __launch_bounds__(256) void chunk_kernel(
    const float* __restrict__ qn, const float* __restrict__ kn,
    const float* __restrict__ kb, const float* __restrict__ vb,
    float* __restrict__ U, float* __restrict__ Wm, float* __restrict__ ATT)
{
    extern __shared__ float sm[];
    float* sk  = sm;            // 32x256
    float* skb = sm + 8192;     // 32x256
    float* sx  = sm + 16384;    // 32x256 (vb then qn)
    float* T   = sm + 24576;    // 32x33
    int bh = blockIdx.x, n = blockIdx.y;
    int tid = threadIdx.x;
    size_t base = ((size_t)bh * L_ + n * C_) * DK_;

    for (int i = tid; i < 2048; i += 256) {
        ((float4*)sk)[i]  = ((const float4*)(kn + base))[i];
        ((float4*)skb)[i] = ((const float4*)(kb + base))[i];
        ((float4*)sx)[i]  = ((const float4*)(vb + base))[i];
    }
    __syncthreads();

    // A = -(kb @ kn^T) * strict_lower
    for (int e = tid; e < 1024; e += 256) {
        int i = e >> 5, j = e & 31;
        float a = 0.f;
        if (j < i) {
            const float* pi = skb + i * 256;
            const float* pj = sk + j * 256;
            for (int d = 0; d < 256; d++) a -= pi[d] * pj[d];
        }
        T[i * 33 + j] = a;
    }
    __syncthreads();

    // forward substitution (warp 0)
    if (tid < 32) {
        int j = tid;
        for (int i = 1; i < 32; i++) {
            float rv = T[i * 33 + j];
            float acc = rv;
            for (int m = 1; m < i; m++)
                acc += __shfl_sync(0xffffffffu, rv, m) * T[m * 33 + j];
            __syncwarp();
            T[i * 33 + j] = acc;
            __syncwarp();
        }
        T[j * 33 + j] = 1.f;
    }
    __syncthreads();

    // u = T @ vb, w = T @ kb
    for (int idx = tid; idx < 8192; idx += 256) {
        int c = idx >> 8, d = idx & 255;
        float au = 0.f, aw = 0.f;
#pragma unroll
        for (int j = 0; j < 32; j++) {
            float t = T[c * 33 + j];
            au += t * sx[j * 256 + d];
            aw += t * skb[j * 256 + d];
        }
        U[base + idx]  = au;
        Wm[base + idx] = aw;
    }
    __syncthreads();

    // attn = (qn @ kn^T) * causal
    for (int i = tid; i < 2048; i += 256)
        ((float4*)sx)[i] = ((const float4*)(qn + base))[i];
    __syncthreads();
    float* att = ATT + ((size_t)bh * NC_ + n) * 1024;
    for (int e = tid; e < 1024; e += 256) {
        int c = e >> 5, j = e & 31;
        float a = 0.f;
        if (j <= c) {
            const float* pq = sx + c * 256;
            const float* pk = sk + j * 256;
            for (int d = 0; d < 256; d++) a += pq[d] * pk[d];
        }
        att[e] = a;
    }
}

// ------------------------- sequential chunk scan (dv tiled by 16) -----------
#define SCAN_SMEM (30720 * 4)
__global__ __launch_bounds__(256) void scan_kernel(
    const float* __restrict__ qn, const float* __restrict__ kn,
    const float* __restrict__ U, const float* __restrict__ Wm,
    const float* __restrict__ ATT, float* __restrict__ OUT)
{
    extern __shared__ float sm[];
    float* S   = sm;            // [256][16]
    float* sq  = sm + 4096;     // [32][256]
    float* sk  = sm + 12288;    // [32][256]
    float* sw  = sm + 20480;    // [32][256]
    float* su  = sm + 28672;    // [32][16]
    float* sut = sm + 29184;    // [32][16]
    float* sat = sm + 29696;    // [32][32]
    const int bh = blockIdx.x, tile = blockIdx.y;
    const int tid = threadIdx.x;
    const int b = bh >> 2, h = bh & 3;
    const int g = tid >> 3, eg = tid & 7;

    for (int i = tid; i < 4096; i += 256) S[i] = 0.f;

    for (int n = 0; n < NC_; n++) {
        __syncthreads();
        size_t base = ((size_t)bh * L_ + n * C_) * 256;
        for (int i = tid; i < 2048; i += 256) {
            ((float4*)sq)[i] = ((const float4*)(qn + base))[i];
            ((float4*)sk)[i] = ((const float4*)(kn + base))[i];
            ((float4*)sw)[i] = ((const float4*)(Wm + base))[i];
        }
        if (tid < 128) {
            int c = tid >> 2, e4 = tid & 3;
            ((float4*)su)[tid] = *(const float4*)(U + base + c * 256 + tile * 16 + e4 * 4);
        }
        ((float4*)sat)[tid] = ((const float4*)(ATT + ((size_t)bh * NC_ + n) * 1024))[tid];
        __syncthreads();

        float2 aw = make_float2(0.f, 0.f);
        float2 aq = make_float2(0.f, 0.f);
        const float* wr = sw + g * 256;
        const float* qr = sq + g * 256;
#pragma unroll 8
        for (int d = 0; d < 256; d++) {
            float2 s2 = *(float2*)(S + d * 16 + eg * 2);
            float wv = wr[d], qv = qr[d];
            aw.x += wv * s2.x; aw.y += wv * s2.y;
            aq.x += qv * s2.x; aq.y += qv * s2.y;
        }
        float2 uv = *(float2*)(su + g * 16 + eg * 2);
        float2 ut = make_float2(uv.x - aw.x, uv.y - aw.y);
        *(float2*)(sut + g * 16 + eg * 2) = ut;
        __syncthreads();

        const float* ar = sat + g * 32;
#pragma unroll
        for (int j = 0; j < 32; j++) {
            float av = ar[j];
            float2 u2 = *(float2*)(sut + j * 16 + eg * 2);
            aq.x += av * u2.x; aq.y += av * u2.y;
        }
        *(float2*)(OUT + (size_t)(b * L_ + n * C_ + g) * H_ + h * 256 + tile * 16 + eg * 2) = aq;

        float2 accS[8];
#pragma unroll
        for (int i = 0; i < 8; i++) accS[i] = make_float2(0.f, 0.f);
        for (int c2 = 0; c2 < 32; c2++) {
            float2 u2 = *(float2*)(sut + c2 * 16 + eg * 2);
            const float* kr = sk + c2 * 256 + g * 8;
            float4 k0 = *(const float4*)(kr);
            float4 k1 = *(const float4*)(kr + 4);
            accS[0].x += k0.x * u2.x; accS[0].y += k0.x * u2.y;
            accS[1].x += k0.y * u2.x; accS[1].y += k0.y * u2.y;
            accS[2].x += k0.z * u2.x; accS[2].y += k0.z * u2.y;
            accS[3].x += k0.w * u2.x; accS[3].y += k0.w * u2.y;
            accS[4].x += k1.x * u2.x; accS[4].y += k1.x * u2.y;
            accS[5].x += k1.y * u2.x; accS[5].y += k1.y * u2.y;
            accS[6].x += k1.z * u2.x; accS[6].y += k1.z * u2.y;
            accS[7].x += k1.w * u2.x; accS[7].y += k1.w * u2.y;
        }
#pragma unroll
        for (int i = 0; i < 8; i++) {
            float2 s2 = *(float2*)(S + (g * 8 + i) * 16 + eg * 2);
            s2.x += accS[i].x; s2.y += accS[i].y;
            *(float2*)(S + (g * 8 + i) * 16 + eg * 2) = s2;
        }
    }
}

// ------------------------- FIR K=7 (unrolled) -------------------------------
__global__ __launch_bounds__(256) void fir7_kernel(
    const float* __restrict__ x, const float* __restrict__ f, float* __restrict__ y)
{
    int idx = blockIdx.x * 256 + threadIdx.x;
    int c  = idx & (H_ - 1);
    int bl = idx >> 10;
    int l  = bl & (L_ - 1);
    const float* fp = f + (size_t)c * 7;
    float acc = 0.f;
#pragma unroll
    for (int t = 0; t < 7; t++) {
        int dl = t - 6;
        if (l + dl >= 0) acc += x[idx + dl * H_] * fp[t];
    }
    y[idx] = acc;
}

// ------------------------- FIR K=64: smem tile + register sliding window ----
#define FIR64_SMEM ((127 * 128 + 64 * 129) * 4)
__global__ __launch_bounds__(256) void fir64_smem_kernel(
    const float* __restrict__ x, const float* __restrict__ f, float* __restrict__ y)
{
    extern __shared__ float fsm[];
    float* sx = fsm;                 // 127 x 128
    float* sf = fsm + 127 * 128;     // 64 x 129
    const int ctile = blockIdx.x & 7;
    const int ltile = blockIdx.x >> 3;
    const int l0 = ltile * 64;
    const int lb = l0 & (L_ - 1);
    const int c0 = ctile * 128;
    const int tid = threadIdx.x;

    for (int i = tid; i < 64 * 128; i += 256) {
        int c = i >> 6, t = i & 63;
        sf[t * 129 + c] = f[(size_t)(c0 + c) * 64 + t];
    }
    for (int i = tid; i < 127 * 128; i += 256) {
        int j = i >> 7, c = i & 127;
        int lrel = lb + j - 63;
        float v = 0.f;
        if (lrel >= 0)
            v = x[(size_t)(l0 + j - 63) * H_ + c0 + c];
        sx[j * 128 + c] = v;
    }
    __syncthreads();

    const int c = tid & 127;
    const int lg = (tid >> 7) * 32;
    float acc[32], win[32];
#pragma unroll
    for (int i = 0; i < 32; i++) acc[i] = 0.f;
#pragma unroll
    for (int i = 0; i < 32; i++) win[i] = sx[(lg + i) * 128 + c];
#pragma unroll
    for (int t = 0; t < 64; t++) {
        float ft = sf[t * 129 + c];
#pragma unroll
        for (int i = 0; i < 32; i++) acc[i] += ft * win[i];
        if (t < 63) {
#pragma unroll
            for (int i = 0; i < 31; i++) win[i] = win[i + 1];
            win[31] = sx[(lg + t + 32) * 128 + c];
        }
    }
#pragma unroll
    for (int i = 0; i < 32; i++)
        y[(size_t)(l0 + lg + i) * H_ + c0 + c] = acc[i];
}

// ------------------------- fusion gate: h1 @ Wf2 + bf2 -> softmax4 ----------
__global__ __launch_bounds__(128) void gate_kernel(
    const float* __restrict__ h1, const float* __restrict__ Wf2,
    const float* __restrict__ bf2, float* __restrict__ fw)
{
    int bl = blockIdx.x, tid = threadIdx.x;
    float acc[16];
#pragma unroll
    for (int j = 0; j < 16; j++) acc[j] = 0.f;
    const float* hp = h1 + (size_t)bl * F1_;
    for (int d = tid; d < F1_; d += 128) {
        float hv = hp[d];
        const float4* w4 = (const float4*)(Wf2 + d * 16);
        float4 w0 = w4[0], w1 = w4[1], w2 = w4[2], w3 = w4[3];
        acc[0] += hv * w0.x; acc[1] += hv * w0.y; acc[2] += hv * w0.z; acc[3] += hv * w0.w;
        acc[4] += hv * w1.x; acc[5] += hv * w1.y; acc[6] += hv * w1.z; acc[7] += hv * w1.w;
        acc[8] += hv * w2.x; acc[9] += hv * w2.y; acc[10] += hv * w2.z; acc[11] += hv * w2.w;
        acc[12] += hv * w3.x; acc[13] += hv * w3.y; acc[14] += hv * w3.z; acc[15] += hv * w3.w;
    }
    __shared__ float red[16][129];
    __shared__ float logit[16];
#pragma unroll
    for (int j = 0; j < 16; j++) red[j][tid] = acc[j];
    __syncthreads();
    if (tid < 16) {
        float s = bf2[tid];
        for (int i = 0; i < 128; i++) s += red[tid][i];
        logit[tid] = s;
    }
    __syncthreads();
    if (tid < 4) {
        float l0 = logit[tid * 4], l1 = logit[tid * 4 + 1];
        float l2 = logit[tid * 4 + 2], l3 = logit[tid * 4 + 3];
        float m = fmaxf(fmaxf(l0, l1), fmaxf(l2, l3));
        float e0 = expf(l0 - m), e1 = expf(l1 - m), e2 = expf(l2 - m), e3 = expf(l3 - m);
        float inv = 1.f / (e0 + e1 + e2 + e3);
        float* o = fw + (size_t)bl * 16 + tid * 4;
        o[0] = e0 * inv; o[1] = e1 * inv; o[2] = e2 * inv; o[3] = e3 * inv;
    }
}

// ------------------------- branch mix + per-head rmsnorm -> bf16 hi/lo ------
__global__ __launch_bounds__(256) void mix_rms_kernel(
    const float* __restrict__ br_s, const float* __restrict__ br_l,
    const float* __restrict__ br_d, const float* __restrict__ br_v,
    const float* __restrict__ fw, const float* __restrict__ rmsw,
    __nv_bfloat16* __restrict__ Mhi, __nv_bfloat16* __restrict__ Mlo)
{
    int bl = blockIdx.x, h = blockIdx.y, d = threadIdx.x;
    size_t i = (size_t)bl * H_ + h * 256 + d;
    const float* f = fw + (size_t)bl * 16 + h * 4;
    float val = f[0] * br_s[i] + f[1] * br_l[i] + f[2] * br_d[i] + f[3] * br_v[i];
    float ss = val * val;
#pragma unroll
    for (int o = 16; o; o >>= 1) ss += __shfl_xor_sync(0xffffffffu, ss, o);
    __shared__ float red[8];
    __shared__ float scale;
    if ((d & 31) == 0) red[d >> 5] = ss;
    __syncthreads();
    if (d == 0) {
        float t = 0.f;
        for (int k = 0; k < 8; k++) t += red[k];
        scale = rsqrtf(t * (1.f / 256.f) + 1e-5f);
    }
    __syncthreads();
    float o = val * scale * rmsw[d];
    __nv_bfloat16 hb = __float2bfloat16(o);
    Mhi[i] = hb;
    Mlo[i] = __float2bfloat16(o - __bfloat162float(hb));
}

// ------------------------- launcher ----------------------------------------
extern "C" void kernel_launch(void* const* d_in, const int* in_sizes, int n_in,
                              void* d_out, int out_size)
{
    const float* hs   = (const float*)d_in[0];
    const float* Wq   = (const float*)d_in[1];
    const float* Wk   = (const float*)d_in[2];
    const float* Wv   = (const float*)d_in[3];
    const float* Wb   = (const float*)d_in[4];
    const float* cq   = (const float*)d_in[5];
    const float* ck   = (const float*)d_in[6];
    const float* cv   = (const float*)d_in[7];
    const float* fsw  = (const float*)d_in[8];
    const float* flw  = (const float*)d_in[9];
    const float* Wf1  = (const float*)d_in[10];
    const float* bf1  = (const float*)d_in[11];
    const float* Wf2  = (const float*)d_in[12];
    const float* bf2  = (const float*)d_in[13];
    const float* rmsw = (const float*)d_in[14];
    const float* Wo   = (const float*)d_in[15];
    float* out = (float*)d_out;

    float *qkvp, *qs, *ks, *vs, *qn, *kn, *kb, *vb;
    float *u, *w, *delta, *shrt, *lng, *h1, *att, *beta, *fw;
    __nv_bfloat16 *ahi, *alo, *mhi, *mlo, *wqh, *wql, *wf1h, *wf1l, *woh, *wol;
    cudaGetSymbolAddress((void**)&qkvp, g_qkvp);
    cudaGetSymbolAddress((void**)&qs, g_qs);
    cudaGetSymbolAddress((void**)&ks, g_ks);
    cudaGetSymbolAddress((void**)&vs, g_vs);
    cudaGetSymbolAddress((void**)&qn, g_qn);
    cudaGetSymbolAddress((void**)&kn, g_kn);
    cudaGetSymbolAddress((void**)&kb, g_kb);
    cudaGetSymbolAddress((void**)&vb, g_vb);
    cudaGetSymbolAddress((void**)&u, g_u);
    cudaGetSymbolAddress((void**)&w, g_w);
    cudaGetSymbolAddress((void**)&delta, g_delta);
    cudaGetSymbolAddress((void**)&shrt, g_shrt);
    cudaGetSymbolAddress((void**)&lng, g_long);
    cudaGetSymbolAddress((void**)&h1, g_h1);
    cudaGetSymbolAddress((void**)&att, g_att);
    cudaGetSymbolAddress((void**)&beta, g_beta);
    cudaGetSymbolAddress((void**)&fw, g_fw);
    cudaGetSymbolAddress((void**)&ahi, g_ahi);
    cudaGetSymbolAddress((void**)&alo, g_alo);
    cudaGetSymbolAddress((void**)&mhi, g_mhi);
    cudaGetSymbolAddress((void**)&mlo, g_mlo);
    cudaGetSymbolAddress((void**)&wqh, g_wqkv_hi);
    cudaGetSymbolAddress((void**)&wql, g_wqkv_lo);
    cudaGetSymbolAddress((void**)&wf1h, g_wf1_hi);
    cudaGetSymbolAddress((void**)&wf1l, g_wf1_lo);
    cudaGetSymbolAddress((void**)&woh, g_wo_hi);
    cudaGetSymbolAddress((void**)&wol, g_wo_lo);

    cudaFuncSetAttribute(mma_gemm2_kernel, cudaFuncAttributeMaxDynamicSharedMemorySize, MG_SMEM);
    cudaFuncSetAttribute(chunk_kernel, cudaFuncAttributeMaxDynamicSharedMemorySize, 102528);
    cudaFuncSetAttribute(scan_kernel,  cudaFuncAttributeMaxDynamicSharedMemorySize, SCAN_SMEM);
    cudaFuncSetAttribute(fir64_smem_kernel, cudaFuncAttributeMaxDynamicSharedMemorySize, FIR64_SMEM);

    // ---- prep: bf16 hi/lo conversions (A once, weights once, transposed) ---
    cvt_a_kernel<<<BL_ * H_ / 1024, 256>>>(hs, ahi, alo);
    cvt_wt_kernel<<<dim3(32, 32), 256>>>(Wq, wqh,             wql,             H_, H_);
    cvt_wt_kernel<<<dim3(32, 32), 256>>>(Wk, wqh + 1024 * H_, wql + 1024 * H_, H_, H_);
    cvt_wt_kernel<<<dim3(32, 32), 256>>>(Wv, wqh + 2048 * H_, wql + 2048 * H_, H_, H_);
    cvt_wt_kernel<<<dim3(64, 32), 256>>>(Wf1, wf1h, wf1l, H_, F1_);
    cvt_wt_kernel<<<dim3(32, 32), 256>>>(Wo, woh, wol, H_, H_);

    // ---- fused qkv projection + gate-MLP first layer -----------------------
    mma_gemm2_kernel<<<dim3(NQKV / 128, BL_ / 128), 256, MG_SMEM>>>(
        ahi, alo, wqh, wql, nullptr, qkvp, NQKV, H_, 0);
    mma_gemm2_kernel<<<dim3(F1_ / 128, BL_ / 128), 256, MG_SMEM>>>(
        ahi, alo, wf1h, wf1l, bf1, h1, F1_, H_, 1);

    // short conv + silu (reads packed qkv)
    conv4_silu_kernel<<<BL_ * H_ / 256, 256>>>(qkvp, cq, qs, NQKV, 0);
    conv4_silu_kernel<<<BL_ * H_ / 256, 256>>>(qkvp, ck, ks, NQKV, 1024);
    conv4_silu_kernel<<<BL_ * H_ / 256, 256>>>(qkvp, cv, vs, NQKV, 2048);

    // beta, l2norm + transpose
    beta_kernel<<<BL_, 128>>>(hs, Wb, beta);
    normtr_kernel<<<dim3(BL_, NH_), 256>>>(qs, ks, vs, beta, qn, kn, kb, vb);

    // delta rule
    chunk_kernel<<<dim3(BH_, NC_), 256, 102528>>>(qn, kn, kb, vb, u, w, att);
    scan_kernel<<<dim3(BH_, 16), 256, SCAN_SMEM>>>(qn, kn, u, w, att, delta);

    // FIR branches
    fir7_kernel<<<BL_ * H_ / 256, 256>>>(vs, fsw, shrt);
    fir64_smem_kernel<<<1024, 256, FIR64_SMEM>>>(vs, flw, lng);

    // gate, mix+rmsnorm (emits bf16 hi/lo), output projection
    gate_kernel<<<BL_, 128>>>(h1, Wf2, bf2, fw);
    mix_rms_kernel<<<dim3(BL_, NH_), 256>>>(shrt, lng, delta, vs, fw, rmsw, mhi, mlo);
    mma_gemm2_kernel<<<dim3(H_ / 128, BL_ / 128), 256, MG_SMEM>>>(
        mhi, mlo, woh, wol, nullptr, out, H_, H_, 0);
}